// round 9
// baseline (speedup 1.0000x reference)
#include <cuda_runtime.h>
#include <math.h>

#define Hdim   768
#define FFdim  3072
#define NLAY   12
#define NHEADS 12
#define DHEAD  64
#define BATCH  4
#define SEQ    512
#define MTOK   (BATCH*SEQ)   // 2048
#define NEnt   12
#define NRel   13

// ---------------- scratch (static device globals; no allocation) -------------
__device__ float g_x[MTOK*Hdim];
__device__ float g_xr[MTOK*Hdim];      // tf32-rounded copy of x (GEMM A side)
__device__ float g_q[MTOK*Hdim];
__device__ float g_k[MTOK*Hdim];
__device__ float g_v[MTOK*Hdim];
__device__ float g_ctx[MTOK*Hdim];
__device__ float g_ffn[MTOK*FFdim];
__device__ float g_pi[MTOK*NRel];
__device__ float g_pj[MTOK*NRel];
__device__ float g_abias[BATCH*SEQ];

// ---------------- tf32 helpers ------------------------------------------------
__device__ __forceinline__ unsigned f2tf(float f) {
    unsigned u;
    asm("cvt.rna.tf32.f32 %0, %1;" : "=r"(u) : "f"(f));
    return u;
}
__device__ __forceinline__ float roundtf(float f) { return __uint_as_float(f2tf(f)); }
__device__ __forceinline__ void mma8(float* c, unsigned a0, unsigned a1,
                                     unsigned a2, unsigned a3,
                                     unsigned b0, unsigned b1) {
    asm volatile(
        "mma.sync.aligned.m16n8k8.row.col.f32.tf32.tf32.f32 "
        "{%0,%1,%2,%3},{%4,%5,%6,%7},{%8,%9},{%0,%1,%2,%3};"
        : "+f"(c[0]), "+f"(c[1]), "+f"(c[2]), "+f"(c[3])
        : "r"(a0), "r"(a1), "r"(a2), "r"(a3), "r"(b0), "r"(b1));
}
#define CPA16(dst, src) \
    asm volatile("cp.async.ca.shared.global [%0], [%1], 16;" :: "r"(dst), "l"(src))
__device__ __forceinline__ void cp_commit() { asm volatile("cp.async.commit_group;"); }

// ---------------- embedding + LayerNorm ---------------------------------------
__global__ __launch_bounds__(256) void embed_ln_kernel(
    const int* __restrict__ ids, const float* __restrict__ ew,
    const float* __restrict__ ep, const float* __restrict__ et,
    const float* __restrict__ g, const float* __restrict__ b)
{
    int t = blockIdx.x;
    int s = t & (SEQ - 1);
    int id = ids[t];
    int tid = threadIdx.x;
    float vals[3];
    float sum = 0.f;
#pragma unroll
    for (int i = 0; i < 3; i++) {
        int c = tid + i * 256;
        vals[i] = ew[(size_t)id * Hdim + c] + ep[(size_t)s * Hdim + c] + et[c];
        sum += vals[i];
    }
    __shared__ float red[256];
    red[tid] = sum; __syncthreads();
    for (int o = 128; o; o >>= 1) { if (tid < o) red[tid] += red[tid + o]; __syncthreads(); }
    float mean = red[0] * (1.f / Hdim);
    __syncthreads();
    float sq = 0.f;
#pragma unroll
    for (int i = 0; i < 3; i++) { float d = vals[i] - mean; sq += d * d; }
    red[tid] = sq; __syncthreads();
    for (int o = 128; o; o >>= 1) { if (tid < o) red[tid] += red[tid + o]; __syncthreads(); }
    float rstd = rsqrtf(red[0] * (1.f / Hdim) + 1e-12f);
#pragma unroll
    for (int i = 0; i < 3; i++) {
        int c = tid + i * 256;
        float v = (vals[i] - mean) * rstd * g[c] + b[c];
        g_x [(size_t)t * Hdim + c] = v;
        g_xr[(size_t)t * Hdim + c] = roundtf(v);
    }
}

// ---------------- residual add + LayerNorm (writes x and xr) ------------------
__global__ __launch_bounds__(256) void add_ln_kernel(
    float* __restrict__ x, const float* __restrict__ y,
    const float* __restrict__ g, const float* __restrict__ b)
{
    int t = blockIdx.x;
    int tid = threadIdx.x;
    float vals[3];
    float sum = 0.f;
#pragma unroll
    for (int i = 0; i < 3; i++) {
        int c = tid + i * 256;
        vals[i] = x[(size_t)t * Hdim + c] + y[(size_t)t * Hdim + c];
        sum += vals[i];
    }
    __shared__ float red[256];
    red[tid] = sum; __syncthreads();
    for (int o = 128; o; o >>= 1) { if (tid < o) red[tid] += red[tid + o]; __syncthreads(); }
    float mean = red[0] * (1.f / Hdim);
    __syncthreads();
    float sq = 0.f;
#pragma unroll
    for (int i = 0; i < 3; i++) { float d = vals[i] - mean; sq += d * d; }
    red[tid] = sq; __syncthreads();
    for (int o = 128; o; o >>= 1) { if (tid < o) red[tid] += red[tid + o]; __syncthreads(); }
    float rstd = rsqrtf(red[0] * (1.f / Hdim) + 1e-12f);
#pragma unroll
    for (int i = 0; i < 3; i++) {
        int c = tid + i * 256;
        float v = (vals[i] - mean) * rstd * g[c] + b[c];
        x[(size_t)t * Hdim + c] = v;
        g_xr[(size_t)t * Hdim + c] = roundtf(v);
    }
}

// ---------------- tf32 GEMM: BM=128 BN=128 BK=16, 256 thr, 4-stage ------------
#define GEMM_STAGES 4
#define GEMM_SMEM   (GEMM_STAGES * (128*20 + 16*136) * 4)   // 75776 bytes
__global__ __launch_bounds__(256, 2) void tf32_gemm_kernel(
    const float* __restrict__ A,
    const float* __restrict__ W0, const float* __restrict__ W1, const float* __restrict__ W2,
    const float* __restrict__ bias0, const float* __restrict__ bias1, const float* __restrict__ bias2,
    float* __restrict__ C0, float* __restrict__ C1, float* __restrict__ C2,
    int M, int N, int K, int act, int rnd)
{
    int z = blockIdx.z;
    const float* W    = (z == 0) ? W0    : (z == 1) ? W1    : W2;
    const float* bias = (z == 0) ? bias0 : (z == 1) ? bias1 : bias2;
    float*       C    = (z == 0) ? C0    : (z == 1) ? C1    : C2;

    extern __shared__ float smem[];
    float (*As)[128][20]  = (float(*)[128][20])smem;
    float (*Bs)[16][136]  = (float(*)[16][136])(smem + GEMM_STAGES*128*20);

    int tid = threadIdx.x;
    int warp = tid >> 5, lane = tid & 31;
    int r = lane >> 2, cq = lane & 3;
    int wm = (warp >> 2) * 64;
    int wn = (warp & 3) * 32;
    int m0 = blockIdx.y * 128, n0 = blockIdx.x * 128;

    float acc[4][4][4];
#pragma unroll
    for (int i = 0; i < 4; i++)
#pragma unroll
        for (int j = 0; j < 4; j++)
#pragma unroll
            for (int t = 0; t < 4; t++) acc[i][j][t] = 0.f;

    int KT = K / 16;

#pragma unroll
    for (int s = 0; s < GEMM_STAGES - 1; s++) {
        int k0 = s * 16;
#pragma unroll
        for (int u = 0; u < 2; u++) {
            int f = tid + u * 256;
            int row = f >> 2, seg = (f & 3) * 4;
            unsigned da = (unsigned)__cvta_generic_to_shared(&As[s][row][seg]);
            CPA16(da, A + (size_t)(m0 + row) * K + k0 + seg);
        }
#pragma unroll
        for (int u = 0; u < 2; u++) {
            int f = tid + u * 256;
            int row = f >> 5, off = (f & 31) * 4;
            unsigned db = (unsigned)__cvta_generic_to_shared(&Bs[s][row][off]);
            CPA16(db, W + (size_t)(k0 + row) * N + n0 + off);
        }
        cp_commit();
    }

    for (int kt = 0; kt < KT; kt++) {
        int cur = kt & (GEMM_STAGES - 1);
        asm volatile("cp.async.wait_group %0;" :: "n"(GEMM_STAGES - 2));
        __syncthreads();

        if (kt + GEMM_STAGES - 1 < KT) {
            int s = (kt + GEMM_STAGES - 1) & (GEMM_STAGES - 1);
            int k0 = (kt + GEMM_STAGES - 1) * 16;
#pragma unroll
            for (int u = 0; u < 2; u++) {
                int f = tid + u * 256;
                int row = f >> 2, seg = (f & 3) * 4;
                unsigned da = (unsigned)__cvta_generic_to_shared(&As[s][row][seg]);
                CPA16(da, A + (size_t)(m0 + row) * K + k0 + seg);
            }
#pragma unroll
            for (int u = 0; u < 2; u++) {
                int f = tid + u * 256;
                int row = f >> 5, off = (f & 31) * 4;
                unsigned db = (unsigned)__cvta_generic_to_shared(&Bs[s][row][off]);
                CPA16(db, W + (size_t)(k0 + row) * N + n0 + off);
            }
        }
        cp_commit();

#pragma unroll
        for (int ks = 0; ks < 2; ks++) {
            int kk = ks * 8;
            unsigned af[4][4], bf[4][2];
#pragma unroll
            for (int mt = 0; mt < 4; mt++) {
                int mr = wm + mt * 16 + r;
                af[mt][0] = __float_as_uint(As[cur][mr    ][kk + cq]);
                af[mt][1] = __float_as_uint(As[cur][mr + 8][kk + cq]);
                af[mt][2] = __float_as_uint(As[cur][mr    ][kk + cq + 4]);
                af[mt][3] = __float_as_uint(As[cur][mr + 8][kk + cq + 4]);
            }
#pragma unroll
            for (int nt = 0; nt < 4; nt++) {
                int nn = wn + nt * 8 + r;
                bf[nt][0] = f2tf(Bs[cur][kk + cq    ][nn]);
                bf[nt][1] = f2tf(Bs[cur][kk + cq + 4][nn]);
            }
#pragma unroll
            for (int mt = 0; mt < 4; mt++)
#pragma unroll
                for (int nt = 0; nt < 4; nt++)
                    mma8(acc[mt][nt], af[mt][0], af[mt][1], af[mt][2], af[mt][3],
                         bf[nt][0], bf[nt][1]);
        }
    }

#pragma unroll
    for (int mt = 0; mt < 4; mt++) {
        int row = m0 + wm + mt * 16 + r;
#pragma unroll
        for (int nt = 0; nt < 4; nt++) {
            int col = n0 + wn + nt * 8 + cq * 2;
            float2 bb = *(const float2*)&bias[col];
            float v0 = acc[mt][nt][0] + bb.x;
            float v1 = acc[mt][nt][1] + bb.y;
            float v2 = acc[mt][nt][2] + bb.x;
            float v3 = acc[mt][nt][3] + bb.y;
            if (act) {
                v0 = 0.5f * v0 * (1.0f + erff(v0 * 0.70710678118654752f));
                v1 = 0.5f * v1 * (1.0f + erff(v1 * 0.70710678118654752f));
                v2 = 0.5f * v2 * (1.0f + erff(v2 * 0.70710678118654752f));
                v3 = 0.5f * v3 * (1.0f + erff(v3 * 0.70710678118654752f));
            }
            if (rnd) {
                v0 = roundtf(v0); v1 = roundtf(v1);
                v2 = roundtf(v2); v3 = roundtf(v3);
            }
            *(float2*)&C[(size_t)row * N + col]       = make_float2(v0, v1);
            *(float2*)&C[(size_t)(row + 8) * N + col] = make_float2(v2, v3);
        }
    }
}

// ---------------- tf32 GEMM: BM=64 BN=64 BK=16, 256 thr, 4-stage --------------
// For N=768 GEMMs (O-proj, FF2): 384 blocks, 3 blocks/SM -> one balanced wave.
#define G64_STAGES 4
#define G64_SMEM   (G64_STAGES * (64*20 + 16*72) * 4)   // 38912 bytes
__global__ __launch_bounds__(256, 3) void tf32_gemm64_kernel(
    const float* __restrict__ A, const float* __restrict__ W,
    const float* __restrict__ bias, float* __restrict__ C,
    int M, int N, int K, int act, int rnd)
{
    extern __shared__ float smem[];
    float (*As)[64][20] = (float(*)[64][20])smem;
    float (*Bs)[16][72] = (float(*)[16][72])(smem + G64_STAGES*64*20);

    int tid = threadIdx.x;
    int warp = tid >> 5, lane = tid & 31;
    int r = lane >> 2, cq = lane & 3;
    int wm = (warp >> 1) * 16;      // 4 m-warps
    int wn = (warp & 1) * 32;       // 2 n-warps
    int m0 = blockIdx.y * 64, n0 = blockIdx.x * 64;

    float acc[4][4];
#pragma unroll
    for (int j = 0; j < 4; j++)
#pragma unroll
        for (int t = 0; t < 4; t++) acc[j][t] = 0.f;

    int KT = K / 16;

#pragma unroll
    for (int s = 0; s < G64_STAGES - 1; s++) {
        int k0 = s * 16;
        {
            int row = tid >> 2, seg = (tid & 3) * 4;
            unsigned da = (unsigned)__cvta_generic_to_shared(&As[s][row][seg]);
            CPA16(da, A + (size_t)(m0 + row) * K + k0 + seg);
        }
        {
            int row = tid >> 4, off = (tid & 15) * 4;
            unsigned db = (unsigned)__cvta_generic_to_shared(&Bs[s][row][off]);
            CPA16(db, W + (size_t)(k0 + row) * N + n0 + off);
        }
        cp_commit();
    }

    for (int kt = 0; kt < KT; kt++) {
        int cur = kt & (G64_STAGES - 1);
        asm volatile("cp.async.wait_group %0;" :: "n"(G64_STAGES - 2));
        __syncthreads();

        if (kt + G64_STAGES - 1 < KT) {
            int s = (kt + G64_STAGES - 1) & (G64_STAGES - 1);
            int k0 = (kt + G64_STAGES - 1) * 16;
            {
                int row = tid >> 2, seg = (tid & 3) * 4;
                unsigned da = (unsigned)__cvta_generic_to_shared(&As[s][row][seg]);
                CPA16(da, A + (size_t)(m0 + row) * K + k0 + seg);
            }
            {
                int row = tid >> 4, off = (tid & 15) * 4;
                unsigned db = (unsigned)__cvta_generic_to_shared(&Bs[s][row][off]);
                CPA16(db, W + (size_t)(k0 + row) * N + n0 + off);
            }
        }
        cp_commit();

#pragma unroll
        for (int ks = 0; ks < 2; ks++) {
            int kk = ks * 8;
            int mr = wm + r;
            unsigned a0 = __float_as_uint(As[cur][mr    ][kk + cq]);
            unsigned a1 = __float_as_uint(As[cur][mr + 8][kk + cq]);
            unsigned a2 = __float_as_uint(As[cur][mr    ][kk + cq + 4]);
            unsigned a3 = __float_as_uint(As[cur][mr + 8][kk + cq + 4]);
#pragma unroll
            for (int nt = 0; nt < 4; nt++) {
                int nn = wn + nt * 8 + r;
                unsigned b0 = f2tf(Bs[cur][kk + cq    ][nn]);
                unsigned b1 = f2tf(Bs[cur][kk + cq + 4][nn]);
                mma8(acc[nt], a0, a1, a2, a3, b0, b1);
            }
        }
    }

#pragma unroll
    for (int nt = 0; nt < 4; nt++) {
        int row = m0 + wm + r;
        int col = n0 + wn + nt * 8 + cq * 2;
        float2 bb = *(const float2*)&bias[col];
        float v0 = acc[nt][0] + bb.x;
        float v1 = acc[nt][1] + bb.y;
        float v2 = acc[nt][2] + bb.x;
        float v3 = acc[nt][3] + bb.y;
        if (act) {
            v0 = 0.5f * v0 * (1.0f + erff(v0 * 0.70710678118654752f));
            v1 = 0.5f * v1 * (1.0f + erff(v1 * 0.70710678118654752f));
            v2 = 0.5f * v2 * (1.0f + erff(v2 * 0.70710678118654752f));
            v3 = 0.5f * v3 * (1.0f + erff(v3 * 0.70710678118654752f));
        }
        if (rnd) {
            v0 = roundtf(v0); v1 = roundtf(v1);
            v2 = roundtf(v2); v3 = roundtf(v3);
        }
        *(float2*)&C[(size_t)row * N + col]       = make_float2(v0, v1);
        *(float2*)&C[(size_t)(row + 8) * N + col] = make_float2(v2, v3);
    }
}

// ---------------- attention-mask bias -----------------------------------------
__global__ void abias_kernel(const int* __restrict__ mask)
{
    int i = blockIdx.x * blockDim.x + threadIdx.x;
    if (i < BATCH * SEQ) g_abias[i] = (1.f - (float)mask[i]) * -10000.f;
}

// ---------------- fused attention: scores + softmax + P@V ---------------------
// grid (SEQ/32, B*NH), 256 thr, i-tile = 32 rows -> 107 KB smem, 2 blocks/SM.
#define ATTN_SMEM ((32*68 + 2*64*68 + 32*516) * 4)   // 109568 bytes
__global__ __launch_bounds__(256, 2) void attn_fused_kernel(
    const float* __restrict__ q, const float* __restrict__ k,
    const float* __restrict__ v, float* __restrict__ ctx)
{
    extern __shared__ float sm[];
    float (*Qs)[68]     = (float(*)[68])sm;                     // 32x68
    float (*Ks)[64][68] = (float(*)[64][68])(sm + 32*68);       // [2][64][68] (K, then V)
    float (*S)[516]     = (float(*)[516])(sm + 32*68 + 2*64*68);// 32x516

    int bh = blockIdx.y;
    int b = bh / NHEADS, h = bh - b * NHEADS;
    int i0 = blockIdx.x * 32;
    int tid = threadIdx.x;
    int warp = tid >> 5, lane = tid & 31;
    int r = lane >> 2, cq = lane & 3;
    int wm = (warp >> 2) * 16;      // scores: 2 m-warps x 16 rows
    int wn = (warp & 3) * 16;       // scores: 4 n-warps x 16 cols

    // load Q tile (32 x 64)
    {
        int c = tid;                 // need 512 float4; 256 threads x 2
#pragma unroll
        for (int u = 0; u < 2; u++) {
            int f = c + u * 256;
            int row = f >> 4, off = (f & 15) << 2;
            *(float4*)&Qs[row][off] =
                *(const float4*)(q + (size_t)(b * SEQ + i0 + row) * Hdim + h * DHEAD + off);
        }
    }
    __syncthreads();

    // Q fragments in registers (one 16-row m-frag per warp)
    unsigned aq[8][4];
#pragma unroll
    for (int ks = 0; ks < 8; ks++) {
        int kk = ks * 8;
        int mr = wm + r;
        aq[ks][0] = __float_as_uint(Qs[mr    ][kk + cq]);
        aq[ks][1] = __float_as_uint(Qs[mr + 8][kk + cq]);
        aq[ks][2] = __float_as_uint(Qs[mr    ][kk + cq + 4]);
        aq[ks][3] = __float_as_uint(Qs[mr + 8][kk + cq + 4]);
    }

    // prologue K tile 0
#pragma unroll
    for (int u = 0; u < 2; u++) {
        int c = tid + u * 256;
        int row = c >> 3, off = (c & 7) << 3;
        const float* src = k + (size_t)(b * SEQ + row) * Hdim + h * DHEAD + off;
        unsigned d = (unsigned)__cvta_generic_to_shared(&Ks[0][row][off]);
        CPA16(d, src); CPA16(d + 16, src + 4);
    }
    cp_commit();

    // ---- scores phase ----
    for (int jt = 0; jt < 8; jt++) {
        int cur = jt & 1;
        __syncthreads();
        if (jt + 1 < 8) {
            int j0 = (jt + 1) * 64;
#pragma unroll
            for (int u = 0; u < 2; u++) {
                int c = tid + u * 256;
                int row = c >> 3, off = (c & 7) << 3;
                const float* src = k + (size_t)(b * SEQ + j0 + row) * Hdim + h * DHEAD + off;
                unsigned d = (unsigned)__cvta_generic_to_shared(&Ks[cur ^ 1][row][off]);
                CPA16(d, src); CPA16(d + 16, src + 4);
            }
        }
        cp_commit();
        asm volatile("cp.async.wait_group 1;");
        __syncthreads();

        float acc[2][4];
#pragma unroll
        for (int j = 0; j < 2; j++)
#pragma unroll
            for (int t = 0; t < 4; t++) acc[j][t] = 0.f;

#pragma unroll
        for (int ks = 0; ks < 8; ks++) {
            int kk = ks * 8;
#pragma unroll
            for (int nt = 0; nt < 2; nt++) {
                int nn = wn + nt * 8 + r;
                unsigned b0 = __float_as_uint(Ks[cur][nn][kk + cq]);
                unsigned b1 = __float_as_uint(Ks[cur][nn][kk + cq + 4]);
                mma8(acc[nt], aq[ks][0], aq[ks][1], aq[ks][2], aq[ks][3], b0, b1);
            }
        }

#pragma unroll
        for (int nt = 0; nt < 2; nt++) {
            int jcol = jt * 64 + wn + nt * 8 + cq * 2;
            float2 ab = *(const float2*)&g_abias[b * SEQ + jcol];
            *(float2*)&S[wm + r][jcol] =
                make_float2(acc[nt][0] * 0.125f + ab.x,
                            acc[nt][1] * 0.125f + ab.y);
            *(float2*)&S[wm + 8 + r][jcol] =
                make_float2(acc[nt][2] * 0.125f + ab.x,
                            acc[nt][3] * 0.125f + ab.y);
        }
    }

    // prefetch V tile 0 (hidden under softmax)
#pragma unroll
    for (int u = 0; u < 2; u++) {
        int c = tid + u * 256;
        int row = c >> 3, off = (c & 7) << 3;
        const float* src = v + (size_t)(b * SEQ + row) * Hdim + h * DHEAD + off;
        unsigned d = (unsigned)__cvta_generic_to_shared(&Ks[0][row][off]);
        CPA16(d, src); CPA16(d + 16, src + 4);
    }
    cp_commit();
    __syncthreads();

    // ---- softmax (rows stay in smem, tf32-rounded) ----
#pragma unroll
    for (int rr = 0; rr < 4; rr++) {
        int row = warp * 4 + rr;
        float vals[16];
        float m = -1e30f;
#pragma unroll
        for (int t = 0; t < 16; t++) {
            vals[t] = S[row][lane + t * 32];
            m = fmaxf(m, vals[t]);
        }
#pragma unroll
        for (int off = 16; off; off >>= 1) m = fmaxf(m, __shfl_xor_sync(0xFFFFFFFFu, m, off));
        float s = 0.f;
#pragma unroll
        for (int t = 0; t < 16; t++) { vals[t] = expf(vals[t] - m); s += vals[t]; }
#pragma unroll
        for (int off = 16; off; off >>= 1) s += __shfl_xor_sync(0xFFFFFFFFu, s, off);
        float inv = 1.f / s;
#pragma unroll
        for (int t = 0; t < 16; t++)
            S[row][lane + t * 32] = roundtf(vals[t] * inv);
    }

    // ---- P@V phase: O(32x64) = S(32x512) @ V(512x64) ----
    int wmv = (warp >> 2) * 16;     // 2 m-warps
    int wnv = (warp & 3) * 16;      // 4 n-warps x 16 cols
    float acco[2][4];
#pragma unroll
    for (int j = 0; j < 2; j++)
#pragma unroll
        for (int t = 0; t < 4; t++) acco[j][t] = 0.f;

    for (int jt = 0; jt < 8; jt++) {
        int cur = jt & 1;
        __syncthreads();
        if (jt + 1 < 8) {
            int j0 = (jt + 1) * 64;
#pragma unroll
            for (int u = 0; u < 2; u++) {
                int c = tid + u * 256;
                int row = c >> 3, off = (c & 7) << 3;
                const float* src = v + (size_t)(b * SEQ + j0 + row) * Hdim + h * DHEAD + off;
                unsigned d = (unsigned)__cvta_generic_to_shared(&Ks[cur ^ 1][row][off]);
                CPA16(d, src); CPA16(d + 16, src + 4);
            }
        }
        cp_commit();
        asm volatile("cp.async.wait_group 1;");
        __syncthreads();

#pragma unroll
        for (int kg = 0; kg < 8; kg++) {
            int kk = kg * 8;
            int scol = jt * 64 + kk;
            unsigned a0 = __float_as_uint(S[wmv + r    ][scol + cq]);
            unsigned a1 = __float_as_uint(S[wmv + r + 8][scol + cq]);
            unsigned a2 = __float_as_uint(S[wmv + r    ][scol + cq + 4]);
            unsigned a3 = __float_as_uint(S[wmv + r + 8][scol + cq + 4]);
#pragma unroll
            for (int nt = 0; nt < 2; nt++) {
                int nn = wnv + nt * 8 + r;
                unsigned b0 = __float_as_uint(Ks[cur][kk + cq    ][nn]);
                unsigned b1 = __float_as_uint(Ks[cur][kk + cq + 4][nn]);
                mma8(acco[nt], a0, a1, a2, a3, b0, b1);
            }
        }
    }

    // epilogue: write ctx (tf32-rounded, feeds O-proj)
#pragma unroll
    for (int nt = 0; nt < 2; nt++) {
        int irow = b * SEQ + i0 + wmv + r;
        int col = h * DHEAD + wnv + nt * 8 + cq * 2;
        *(float2*)&ctx[(size_t)irow * Hdim + col] =
            make_float2(roundtf(acco[nt][0]), roundtf(acco[nt][1]));
        *(float2*)&ctx[(size_t)(irow + 8) * Hdim + col] =
            make_float2(roundtf(acco[nt][2]), roundtf(acco[nt][3]));
    }
}

// ---------------- heads: entity logits + pi/pj for relations ------------------
__global__ __launch_bounds__(256) void heads_kernel(
    const float* __restrict__ x, const float* __restrict__ W_ent,
    const float* __restrict__ b_ent, const float* __restrict__ W_rel,
    const float* __restrict__ b_rel, float* __restrict__ ent_out)
{
    int t = blockIdx.x;
    int tid = threadIdx.x;
    __shared__ float xs[Hdim];
    for (int i = tid; i < Hdim; i += 256) xs[i] = x[(size_t)t * Hdim + i];
    __syncthreads();
    int warp = tid >> 5, lane = tid & 31;
    for (int o = warp; o < NEnt + 2 * NRel; o += 8) {
        float s = 0.f;
        if (o < NEnt) {
            for (int k = lane; k < Hdim; k += 32) s += xs[k] * W_ent[(size_t)k * NEnt + o];
        } else if (o < NEnt + NRel) {
            int rr = o - NEnt;
            for (int k = lane; k < Hdim; k += 32) s += xs[k] * W_rel[(size_t)k * NRel + rr];
        } else {
            int rr = o - NEnt - NRel;
            for (int k = lane; k < Hdim; k += 32) s += xs[k] * W_rel[(size_t)(Hdim + k) * NRel + rr];
        }
#pragma unroll
        for (int off = 16; off; off >>= 1) s += __shfl_xor_sync(0xFFFFFFFFu, s, off);
        if (lane == 0) {
            if (o < NEnt)             ent_out[(size_t)t * NEnt + o] = s + b_ent[o];
            else if (o < NEnt + NRel) g_pi[t * NRel + (o - NEnt)] = s;
            else                      g_pj[t * NRel + (o - NEnt - NRel)] = s + b_rel[o - NEnt - NRel];
        }
    }
}

// ---------------- relation broadcast ------------------------------------------
__global__ __launch_bounds__(256) void relation_kernel(float* __restrict__ out)
{
    int bi = blockIdx.x;
    int b = bi >> 9;
    __shared__ float ps[NRel];
    if (threadIdx.x < NRel) ps[threadIdx.x] = g_pi[bi * NRel + threadIdx.x];
    __syncthreads();
    const float* pjb = g_pj + (size_t)(b << 9) * NRel;
    float* o = out + (size_t)bi * SEQ * NRel;
    for (int idx = threadIdx.x; idx < SEQ * NRel; idx += 256) {
        int r = idx % NRel;
        o[idx] = ps[r] + pjb[idx];
    }
}

// ---------------- host orchestration -----------------------------------------
extern "C" void kernel_launch(void* const* d_in, const int* in_sizes, int n_in,
                              void* d_out, int out_size)
{
    const int*   input_ids = (const int*)  d_in[0];
    const int*   attn_mask = (const int*)  d_in[1];
    const float* emb_word  = (const float*)d_in[2];
    const float* emb_pos   = (const float*)d_in[3];
    const float* emb_type  = (const float*)d_in[4];
    const float* emb_ln_g  = (const float*)d_in[5];
    const float* emb_ln_b  = (const float*)d_in[6];
    const float* Wq = (const float*)d_in[7];
    const float* bq = (const float*)d_in[8];
    const float* Wk = (const float*)d_in[9];
    const float* bk = (const float*)d_in[10];
    const float* Wv = (const float*)d_in[11];
    const float* bv = (const float*)d_in[12];
    const float* Wo = (const float*)d_in[13];
    const float* bo = (const float*)d_in[14];
    const float* ln1_g = (const float*)d_in[15];
    const float* ln1_b = (const float*)d_in[16];
    const float* W1 = (const float*)d_in[17];
    const float* b1 = (const float*)d_in[18];
    const float* W2 = (const float*)d_in[19];
    const float* b2 = (const float*)d_in[20];
    const float* ln2_g = (const float*)d_in[21];
    const float* ln2_b = (const float*)d_in[22];
    const float* W_ent = (const float*)d_in[23];
    const float* b_ent = (const float*)d_in[24];
    const float* W_rel = (const float*)d_in[25];
    const float* b_rel = (const float*)d_in[26];

    float *x, *xr, *q, *k, *v, *ctx, *ffn;
    cudaGetSymbolAddress((void**)&x,   g_x);
    cudaGetSymbolAddress((void**)&xr,  g_xr);
    cudaGetSymbolAddress((void**)&q,   g_q);
    cudaGetSymbolAddress((void**)&k,   g_k);
    cudaGetSymbolAddress((void**)&v,   g_v);
    cudaGetSymbolAddress((void**)&ctx, g_ctx);
    cudaGetSymbolAddress((void**)&ffn, g_ffn);

    cudaFuncSetAttribute(attn_fused_kernel,
                         cudaFuncAttributeMaxDynamicSharedMemorySize, ATTN_SMEM);
    cudaFuncSetAttribute(tf32_gemm_kernel,
                         cudaFuncAttributeMaxDynamicSharedMemorySize, GEMM_SMEM);
    cudaFuncSetAttribute(tf32_gemm64_kernel,
                         cudaFuncAttributeMaxDynamicSharedMemorySize, G64_SMEM);

    embed_ln_kernel<<<MTOK, 256>>>(input_ids, emb_word, emb_pos, emb_type,
                                   emb_ln_g, emb_ln_b);
    abias_kernel<<<(BATCH * SEQ + 255) / 256, 256>>>(attn_mask);

    dim3 gQKV(Hdim / 128, MTOK / 128, 3);
    dim3 gF1(FFdim / 128, MTOK / 128, 1);
    dim3 g64(Hdim / 64, MTOK / 64);           // 12 x 32 = 384 blocks
    dim3 gA(SEQ / 32, BATCH * NHEADS);        // 16 x 48 = 768 blocks

    for (int l = 0; l < NLAY; l++) {
        size_t wHH = (size_t)l * Hdim * Hdim;
        size_t wH  = (size_t)l * Hdim;
        size_t wHF = (size_t)l * Hdim * FFdim;
        tf32_gemm_kernel<<<gQKV, 256, GEMM_SMEM>>>(xr, Wq + wHH, Wk + wHH, Wv + wHH,
                                        bq + wH, bk + wH, bv + wH,
                                        q, k, v, MTOK, Hdim, Hdim, 0, 1);
        attn_fused_kernel<<<gA, 256, ATTN_SMEM>>>(q, k, v, ctx);
        tf32_gemm64_kernel<<<g64, 256, G64_SMEM>>>(ctx, Wo + wHH, bo + wH,
                                                   q, MTOK, Hdim, Hdim, 0, 0);
        add_ln_kernel<<<MTOK, 256>>>(x, q, ln1_g + wH, ln1_b + wH);
        tf32_gemm_kernel<<<gF1, 256, GEMM_SMEM>>>(xr, W1 + wHF, W1 + wHF, W1 + wHF,
                                       b1 + (size_t)l * FFdim, b1 + (size_t)l * FFdim, b1 + (size_t)l * FFdim,
                                       ffn, ffn, ffn, MTOK, FFdim, Hdim, 1, 1);
        tf32_gemm64_kernel<<<g64, 256, G64_SMEM>>>(ffn, W2 + wHF, b2 + wH,
                                                   q, MTOK, Hdim, FFdim, 0, 0);
        add_ln_kernel<<<MTOK, 256>>>(x, q, ln2_g + wH, ln2_b + wH);
    }

    float* out = (float*)d_out;
    heads_kernel<<<MTOK, 256>>>(x, W_ent, b_ent, W_rel, b_rel, out);
    relation_kernel<<<MTOK, 256>>>(out + (size_t)MTOK * NEnt);
}

// round 10
// speedup vs baseline: 1.0272x; 1.0272x over previous
#include <cuda_runtime.h>
#include <math.h>

#define Hdim   768
#define FFdim  3072
#define NLAY   12
#define NHEADS 12
#define DHEAD  64
#define BATCH  4
#define SEQ    512
#define MTOK   (BATCH*SEQ)   // 2048
#define NEnt   12
#define NRel   13

// ---------------- scratch (static device globals; no allocation) -------------
__device__ float g_x[MTOK*Hdim];
__device__ float g_xr[MTOK*Hdim];      // tf32-rounded copy of x (GEMM A side)
__device__ float g_q[MTOK*Hdim];
__device__ float g_k[MTOK*Hdim];
__device__ float g_v[MTOK*Hdim];
__device__ float g_ctx[MTOK*Hdim];
__device__ float g_ffn[MTOK*FFdim];
__device__ float g_pi[MTOK*NRel];
__device__ float g_pj[MTOK*NRel];
__device__ float g_abias[BATCH*SEQ];

// ---------------- tf32 helpers ------------------------------------------------
__device__ __forceinline__ unsigned f2tf(float f) {
    unsigned u;
    asm("cvt.rna.tf32.f32 %0, %1;" : "=r"(u) : "f"(f));
    return u;
}
__device__ __forceinline__ float roundtf(float f) { return __uint_as_float(f2tf(f)); }
__device__ __forceinline__ void mma8(float* c, unsigned a0, unsigned a1,
                                     unsigned a2, unsigned a3,
                                     unsigned b0, unsigned b1) {
    asm volatile(
        "mma.sync.aligned.m16n8k8.row.col.f32.tf32.tf32.f32 "
        "{%0,%1,%2,%3},{%4,%5,%6,%7},{%8,%9},{%0,%1,%2,%3};"
        : "+f"(c[0]), "+f"(c[1]), "+f"(c[2]), "+f"(c[3])
        : "r"(a0), "r"(a1), "r"(a2), "r"(a3), "r"(b0), "r"(b1));
}
#define CPA16(dst, src) \
    asm volatile("cp.async.ca.shared.global [%0], [%1], 16;" :: "r"(dst), "l"(src))
__device__ __forceinline__ void cp_commit() { asm volatile("cp.async.commit_group;"); }

// ---------------- embedding + LayerNorm ---------------------------------------
__global__ __launch_bounds__(256) void embed_ln_kernel(
    const int* __restrict__ ids, const float* __restrict__ ew,
    const float* __restrict__ ep, const float* __restrict__ et,
    const float* __restrict__ g, const float* __restrict__ b)
{
    int t = blockIdx.x;
    int s = t & (SEQ - 1);
    int id = ids[t];
    int tid = threadIdx.x;
    float vals[3];
    float sum = 0.f;
#pragma unroll
    for (int i = 0; i < 3; i++) {
        int c = tid + i * 256;
        vals[i] = ew[(size_t)id * Hdim + c] + ep[(size_t)s * Hdim + c] + et[c];
        sum += vals[i];
    }
    __shared__ float red[256];
    red[tid] = sum; __syncthreads();
    for (int o = 128; o; o >>= 1) { if (tid < o) red[tid] += red[tid + o]; __syncthreads(); }
    float mean = red[0] * (1.f / Hdim);
    __syncthreads();
    float sq = 0.f;
#pragma unroll
    for (int i = 0; i < 3; i++) { float d = vals[i] - mean; sq += d * d; }
    red[tid] = sq; __syncthreads();
    for (int o = 128; o; o >>= 1) { if (tid < o) red[tid] += red[tid + o]; __syncthreads(); }
    float rstd = rsqrtf(red[0] * (1.f / Hdim) + 1e-12f);
#pragma unroll
    for (int i = 0; i < 3; i++) {
        int c = tid + i * 256;
        float v = (vals[i] - mean) * rstd * g[c] + b[c];
        g_x [(size_t)t * Hdim + c] = v;
        g_xr[(size_t)t * Hdim + c] = roundtf(v);
    }
}

// ---------------- residual add + LayerNorm (writes x and xr) ------------------
__global__ __launch_bounds__(256) void add_ln_kernel(
    float* __restrict__ x, const float* __restrict__ y,
    const float* __restrict__ g, const float* __restrict__ b)
{
    int t = blockIdx.x;
    int tid = threadIdx.x;
    float vals[3];
    float sum = 0.f;
#pragma unroll
    for (int i = 0; i < 3; i++) {
        int c = tid + i * 256;
        vals[i] = x[(size_t)t * Hdim + c] + y[(size_t)t * Hdim + c];
        sum += vals[i];
    }
    __shared__ float red[256];
    red[tid] = sum; __syncthreads();
    for (int o = 128; o; o >>= 1) { if (tid < o) red[tid] += red[tid + o]; __syncthreads(); }
    float mean = red[0] * (1.f / Hdim);
    __syncthreads();
    float sq = 0.f;
#pragma unroll
    for (int i = 0; i < 3; i++) { float d = vals[i] - mean; sq += d * d; }
    red[tid] = sq; __syncthreads();
    for (int o = 128; o; o >>= 1) { if (tid < o) red[tid] += red[tid + o]; __syncthreads(); }
    float rstd = rsqrtf(red[0] * (1.f / Hdim) + 1e-12f);
#pragma unroll
    for (int i = 0; i < 3; i++) {
        int c = tid + i * 256;
        float v = (vals[i] - mean) * rstd * g[c] + b[c];
        x[(size_t)t * Hdim + c] = v;
        g_xr[(size_t)t * Hdim + c] = roundtf(v);
    }
}

// ---------------- tf32 GEMM: BM=128 BN=128 BK=16, 256 thr, 4-stage ------------
#define GEMM_STAGES 4
#define GEMM_SMEM   (GEMM_STAGES * (128*20 + 16*136) * 4)   // 75776 bytes
__global__ __launch_bounds__(256, 2) void tf32_gemm_kernel(
    const float* __restrict__ A,
    const float* __restrict__ W0, const float* __restrict__ W1, const float* __restrict__ W2,
    const float* __restrict__ bias0, const float* __restrict__ bias1, const float* __restrict__ bias2,
    float* __restrict__ C0, float* __restrict__ C1, float* __restrict__ C2,
    int M, int N, int K, int act, int rnd)
{
    int z = blockIdx.z;
    const float* W    = (z == 0) ? W0    : (z == 1) ? W1    : W2;
    const float* bias = (z == 0) ? bias0 : (z == 1) ? bias1 : bias2;
    float*       C    = (z == 0) ? C0    : (z == 1) ? C1    : C2;

    extern __shared__ float smem[];
    float (*As)[128][20]  = (float(*)[128][20])smem;
    float (*Bs)[16][136]  = (float(*)[16][136])(smem + GEMM_STAGES*128*20);

    int tid = threadIdx.x;
    int warp = tid >> 5, lane = tid & 31;
    int r = lane >> 2, cq = lane & 3;
    int wm = (warp >> 2) * 64;
    int wn = (warp & 3) * 32;
    int m0 = blockIdx.y * 128, n0 = blockIdx.x * 128;

    float acc[4][4][4];
#pragma unroll
    for (int i = 0; i < 4; i++)
#pragma unroll
        for (int j = 0; j < 4; j++)
#pragma unroll
            for (int t = 0; t < 4; t++) acc[i][j][t] = 0.f;

    int KT = K / 16;

#pragma unroll
    for (int s = 0; s < GEMM_STAGES - 1; s++) {
        int k0 = s * 16;
#pragma unroll
        for (int u = 0; u < 2; u++) {
            int f = tid + u * 256;
            int row = f >> 2, seg = (f & 3) * 4;
            unsigned da = (unsigned)__cvta_generic_to_shared(&As[s][row][seg]);
            CPA16(da, A + (size_t)(m0 + row) * K + k0 + seg);
        }
#pragma unroll
        for (int u = 0; u < 2; u++) {
            int f = tid + u * 256;
            int row = f >> 5, off = (f & 31) * 4;
            unsigned db = (unsigned)__cvta_generic_to_shared(&Bs[s][row][off]);
            CPA16(db, W + (size_t)(k0 + row) * N + n0 + off);
        }
        cp_commit();
    }

    for (int kt = 0; kt < KT; kt++) {
        int cur = kt & (GEMM_STAGES - 1);
        asm volatile("cp.async.wait_group %0;" :: "n"(GEMM_STAGES - 2));
        __syncthreads();

        if (kt + GEMM_STAGES - 1 < KT) {
            int s = (kt + GEMM_STAGES - 1) & (GEMM_STAGES - 1);
            int k0 = (kt + GEMM_STAGES - 1) * 16;
#pragma unroll
            for (int u = 0; u < 2; u++) {
                int f = tid + u * 256;
                int row = f >> 2, seg = (f & 3) * 4;
                unsigned da = (unsigned)__cvta_generic_to_shared(&As[s][row][seg]);
                CPA16(da, A + (size_t)(m0 + row) * K + k0 + seg);
            }
#pragma unroll
            for (int u = 0; u < 2; u++) {
                int f = tid + u * 256;
                int row = f >> 5, off = (f & 31) * 4;
                unsigned db = (unsigned)__cvta_generic_to_shared(&Bs[s][row][off]);
                CPA16(db, W + (size_t)(k0 + row) * N + n0 + off);
            }
        }
        cp_commit();

#pragma unroll
        for (int ks = 0; ks < 2; ks++) {
            int kk = ks * 8;
            unsigned af[4][4], bf[4][2];
#pragma unroll
            for (int mt = 0; mt < 4; mt++) {
                int mr = wm + mt * 16 + r;
                af[mt][0] = __float_as_uint(As[cur][mr    ][kk + cq]);
                af[mt][1] = __float_as_uint(As[cur][mr + 8][kk + cq]);
                af[mt][2] = __float_as_uint(As[cur][mr    ][kk + cq + 4]);
                af[mt][3] = __float_as_uint(As[cur][mr + 8][kk + cq + 4]);
            }
#pragma unroll
            for (int nt = 0; nt < 4; nt++) {
                int nn = wn + nt * 8 + r;
                bf[nt][0] = f2tf(Bs[cur][kk + cq    ][nn]);
                bf[nt][1] = f2tf(Bs[cur][kk + cq + 4][nn]);
            }
#pragma unroll
            for (int mt = 0; mt < 4; mt++)
#pragma unroll
                for (int nt = 0; nt < 4; nt++)
                    mma8(acc[mt][nt], af[mt][0], af[mt][1], af[mt][2], af[mt][3],
                         bf[nt][0], bf[nt][1]);
        }
    }

#pragma unroll
    for (int mt = 0; mt < 4; mt++) {
        int row = m0 + wm + mt * 16 + r;
#pragma unroll
        for (int nt = 0; nt < 4; nt++) {
            int col = n0 + wn + nt * 8 + cq * 2;
            float2 bb = *(const float2*)&bias[col];
            float v0 = acc[mt][nt][0] + bb.x;
            float v1 = acc[mt][nt][1] + bb.y;
            float v2 = acc[mt][nt][2] + bb.x;
            float v3 = acc[mt][nt][3] + bb.y;
            if (act) {
                v0 = 0.5f * v0 * (1.0f + erff(v0 * 0.70710678118654752f));
                v1 = 0.5f * v1 * (1.0f + erff(v1 * 0.70710678118654752f));
                v2 = 0.5f * v2 * (1.0f + erff(v2 * 0.70710678118654752f));
                v3 = 0.5f * v3 * (1.0f + erff(v3 * 0.70710678118654752f));
            }
            if (rnd) {
                v0 = roundtf(v0); v1 = roundtf(v1);
                v2 = roundtf(v2); v3 = roundtf(v3);
            }
            *(float2*)&C[(size_t)row * N + col]       = make_float2(v0, v1);
            *(float2*)&C[(size_t)(row + 8) * N + col] = make_float2(v2, v3);
        }
    }
}

// ---------------- tf32 GEMM: BM=64 BN=128 BK=16, 256 thr, 4-stage -------------
// For N=768 GEMMs (O-proj, FF2): 192 blocks, 2 blocks/SM (round-8 shape).
#define G64_STAGES 4
#define G64_SMEM   (G64_STAGES * (64*20 + 16*136) * 4)   // 55296 bytes
__global__ __launch_bounds__(256, 2) void tf32_gemm64_kernel(
    const float* __restrict__ A, const float* __restrict__ W,
    const float* __restrict__ bias, float* __restrict__ C,
    int M, int N, int K, int act, int rnd)
{
    extern __shared__ float smem[];
    float (*As)[64][20]  = (float(*)[64][20])smem;
    float (*Bs)[16][136] = (float(*)[16][136])(smem + G64_STAGES*64*20);

    int tid = threadIdx.x;
    int warp = tid >> 5, lane = tid & 31;
    int r = lane >> 2, cq = lane & 3;
    int wm = (warp >> 2) * 32;
    int wn = (warp & 3) * 32;
    int m0 = blockIdx.y * 64, n0 = blockIdx.x * 128;

    float acc[2][4][4];
#pragma unroll
    for (int i = 0; i < 2; i++)
#pragma unroll
        for (int j = 0; j < 4; j++)
#pragma unroll
            for (int t = 0; t < 4; t++) acc[i][j][t] = 0.f;

    int KT = K / 16;

#pragma unroll
    for (int s = 0; s < G64_STAGES - 1; s++) {
        int k0 = s * 16;
        {
            int row = tid >> 2, seg = (tid & 3) * 4;
            unsigned da = (unsigned)__cvta_generic_to_shared(&As[s][row][seg]);
            CPA16(da, A + (size_t)(m0 + row) * K + k0 + seg);
        }
#pragma unroll
        for (int u = 0; u < 2; u++) {
            int f = tid + u * 256;
            int row = f >> 5, off = (f & 31) * 4;
            unsigned db = (unsigned)__cvta_generic_to_shared(&Bs[s][row][off]);
            CPA16(db, W + (size_t)(k0 + row) * N + n0 + off);
        }
        cp_commit();
    }

    for (int kt = 0; kt < KT; kt++) {
        int cur = kt & (G64_STAGES - 1);
        asm volatile("cp.async.wait_group %0;" :: "n"(G64_STAGES - 2));
        __syncthreads();

        if (kt + G64_STAGES - 1 < KT) {
            int s = (kt + G64_STAGES - 1) & (G64_STAGES - 1);
            int k0 = (kt + G64_STAGES - 1) * 16;
            {
                int row = tid >> 2, seg = (tid & 3) * 4;
                unsigned da = (unsigned)__cvta_generic_to_shared(&As[s][row][seg]);
                CPA16(da, A + (size_t)(m0 + row) * K + k0 + seg);
            }
#pragma unroll
            for (int u = 0; u < 2; u++) {
                int f = tid + u * 256;
                int row = f >> 5, off = (f & 31) * 4;
                unsigned db = (unsigned)__cvta_generic_to_shared(&Bs[s][row][off]);
                CPA16(db, W + (size_t)(k0 + row) * N + n0 + off);
            }
        }
        cp_commit();

#pragma unroll
        for (int ks = 0; ks < 2; ks++) {
            int kk = ks * 8;
            unsigned af[2][4], bf[4][2];
#pragma unroll
            for (int mt = 0; mt < 2; mt++) {
                int mr = wm + mt * 16 + r;
                af[mt][0] = __float_as_uint(As[cur][mr    ][kk + cq]);
                af[mt][1] = __float_as_uint(As[cur][mr + 8][kk + cq]);
                af[mt][2] = __float_as_uint(As[cur][mr    ][kk + cq + 4]);
                af[mt][3] = __float_as_uint(As[cur][mr + 8][kk + cq + 4]);
            }
#pragma unroll
            for (int nt = 0; nt < 4; nt++) {
                int nn = wn + nt * 8 + r;
                bf[nt][0] = f2tf(Bs[cur][kk + cq    ][nn]);
                bf[nt][1] = f2tf(Bs[cur][kk + cq + 4][nn]);
            }
#pragma unroll
            for (int mt = 0; mt < 2; mt++)
#pragma unroll
                for (int nt = 0; nt < 4; nt++)
                    mma8(acc[mt][nt], af[mt][0], af[mt][1], af[mt][2], af[mt][3],
                         bf[nt][0], bf[nt][1]);
        }
    }

#pragma unroll
    for (int mt = 0; mt < 2; mt++) {
        int row = m0 + wm + mt * 16 + r;
#pragma unroll
        for (int nt = 0; nt < 4; nt++) {
            int col = n0 + wn + nt * 8 + cq * 2;
            float2 bb = *(const float2*)&bias[col];
            float v0 = acc[mt][nt][0] + bb.x;
            float v1 = acc[mt][nt][1] + bb.y;
            float v2 = acc[mt][nt][2] + bb.x;
            float v3 = acc[mt][nt][3] + bb.y;
            if (act) {
                v0 = 0.5f * v0 * (1.0f + erff(v0 * 0.70710678118654752f));
                v1 = 0.5f * v1 * (1.0f + erff(v1 * 0.70710678118654752f));
                v2 = 0.5f * v2 * (1.0f + erff(v2 * 0.70710678118654752f));
                v3 = 0.5f * v3 * (1.0f + erff(v3 * 0.70710678118654752f));
            }
            if (rnd) {
                v0 = roundtf(v0); v1 = roundtf(v1);
                v2 = roundtf(v2); v3 = roundtf(v3);
            }
            *(float2*)&C[(size_t)row * N + col]       = make_float2(v0, v1);
            *(float2*)&C[(size_t)(row + 8) * N + col] = make_float2(v2, v3);
        }
    }
}

// ---------------- attention-mask bias -----------------------------------------
__global__ void abias_kernel(const int* __restrict__ mask)
{
    int i = blockIdx.x * blockDim.x + threadIdx.x;
    if (i < BATCH * SEQ) g_abias[i] = (1.f - (float)mask[i]) * -10000.f;
}

// ---------------- fused attention: scores + softmax + P@V ---------------------
// grid (SEQ/64, B*NH), 512 thr (16 warps). 64-row i-tile (round-8 traffic),
// doubled warp parallelism. Probabilities never touch gmem.
#define ATTN_SMEM ((64*68 + 2*64*68 + 64*516) * 4)   // 184320 bytes
__global__ __launch_bounds__(512) void attn_fused_kernel(
    const float* __restrict__ q, const float* __restrict__ k,
    const float* __restrict__ v, float* __restrict__ ctx)
{
    extern __shared__ float sm[];
    float (*Qs)[68]     = (float(*)[68])sm;                     // 64x68
    float (*Ks)[64][68] = (float(*)[64][68])(sm + 64*68);       // [2][64][68] (K, then V)
    float (*S)[516]     = (float(*)[516])(sm + 3*64*68);        // 64x516

    int bh = blockIdx.y;
    int b = bh / NHEADS, h = bh - b * NHEADS;
    int i0 = blockIdx.x * 64;
    int tid = threadIdx.x;
    int warp = tid >> 5, lane = tid & 31;
    int r = lane >> 2, cq = lane & 3;
    int wm = (warp >> 2) * 16;      // 4 m-warps x 16 rows
    int wn = (warp & 3) * 16;       // 4 n-warps x 16 cols

    // load Q tile (64 x 64): 1024 float4, 512 threads x 2
#pragma unroll
    for (int u = 0; u < 2; u++) {
        int f = tid + u * 512;
        int row = f >> 4, off = (f & 15) << 2;
        *(float4*)&Qs[row][off] =
            *(const float4*)(q + (size_t)(b * SEQ + i0 + row) * Hdim + h * DHEAD + off);
    }
    __syncthreads();

    // Q fragments in registers (one 16-row m-frag per warp)
    unsigned aq[8][4];
#pragma unroll
    for (int ks = 0; ks < 8; ks++) {
        int kk = ks * 8;
        int mr = wm + r;
        aq[ks][0] = __float_as_uint(Qs[mr    ][kk + cq]);
        aq[ks][1] = __float_as_uint(Qs[mr + 8][kk + cq]);
        aq[ks][2] = __float_as_uint(Qs[mr    ][kk + cq + 4]);
        aq[ks][3] = __float_as_uint(Qs[mr + 8][kk + cq + 4]);
    }

    // prologue K tile 0: 64 rows x 64 floats; 512 threads x (2x16B)
    {
        int row = tid >> 3, off = (tid & 7) << 3;
        const float* src = k + (size_t)(b * SEQ + row) * Hdim + h * DHEAD + off;
        unsigned d = (unsigned)__cvta_generic_to_shared(&Ks[0][row][off]);
        CPA16(d, src); CPA16(d + 16, src + 4);
    }
    cp_commit();

    // ---- scores phase ----
    for (int jt = 0; jt < 8; jt++) {
        int cur = jt & 1;
        __syncthreads();
        if (jt + 1 < 8) {
            int j0 = (jt + 1) * 64;
            int row = tid >> 3, off = (tid & 7) << 3;
            const float* src = k + (size_t)(b * SEQ + j0 + row) * Hdim + h * DHEAD + off;
            unsigned d = (unsigned)__cvta_generic_to_shared(&Ks[cur ^ 1][row][off]);
            CPA16(d, src); CPA16(d + 16, src + 4);
        }
        cp_commit();
        asm volatile("cp.async.wait_group 1;");
        __syncthreads();

        float acc[2][4];
#pragma unroll
        for (int j = 0; j < 2; j++)
#pragma unroll
            for (int t = 0; t < 4; t++) acc[j][t] = 0.f;

#pragma unroll
        for (int ks = 0; ks < 8; ks++) {
            int kk = ks * 8;
#pragma unroll
            for (int nt = 0; nt < 2; nt++) {
                int nn = wn + nt * 8 + r;
                unsigned b0 = __float_as_uint(Ks[cur][nn][kk + cq]);
                unsigned b1 = __float_as_uint(Ks[cur][nn][kk + cq + 4]);
                mma8(acc[nt], aq[ks][0], aq[ks][1], aq[ks][2], aq[ks][3], b0, b1);
            }
        }

#pragma unroll
        for (int nt = 0; nt < 2; nt++) {
            int jcol = jt * 64 + wn + nt * 8 + cq * 2;
            float2 ab = *(const float2*)&g_abias[b * SEQ + jcol];
            *(float2*)&S[wm + r][jcol] =
                make_float2(acc[nt][0] * 0.125f + ab.x,
                            acc[nt][1] * 0.125f + ab.y);
            *(float2*)&S[wm + 8 + r][jcol] =
                make_float2(acc[nt][2] * 0.125f + ab.x,
                            acc[nt][3] * 0.125f + ab.y);
        }
    }

    // prefetch V tile 0 (hidden under softmax)
    {
        int row = tid >> 3, off = (tid & 7) << 3;
        const float* src = v + (size_t)(b * SEQ + row) * Hdim + h * DHEAD + off;
        unsigned d = (unsigned)__cvta_generic_to_shared(&Ks[0][row][off]);
        CPA16(d, src); CPA16(d + 16, src + 4);
    }
    cp_commit();
    __syncthreads();

    // ---- softmax: 16 warps x 4 rows (rows stay in smem, tf32-rounded) ----
#pragma unroll
    for (int rr = 0; rr < 4; rr++) {
        int row = warp * 4 + rr;
        float vals[16];
        float m = -1e30f;
#pragma unroll
        for (int t = 0; t < 16; t++) {
            vals[t] = S[row][lane + t * 32];
            m = fmaxf(m, vals[t]);
        }
#pragma unroll
        for (int off = 16; off; off >>= 1) m = fmaxf(m, __shfl_xor_sync(0xFFFFFFFFu, m, off));
        float s = 0.f;
#pragma unroll
        for (int t = 0; t < 16; t++) { vals[t] = expf(vals[t] - m); s += vals[t]; }
#pragma unroll
        for (int off = 16; off; off >>= 1) s += __shfl_xor_sync(0xFFFFFFFFu, s, off);
        float inv = 1.f / s;
#pragma unroll
        for (int t = 0; t < 16; t++)
            S[row][lane + t * 32] = roundtf(vals[t] * inv);
    }

    // ---- P@V phase: O(64x64) = S(64x512) @ V(512x64); 4m x 4n warps ----
    float acco[2][4];
#pragma unroll
    for (int j = 0; j < 2; j++)
#pragma unroll
        for (int t = 0; t < 4; t++) acco[j][t] = 0.f;

    for (int jt = 0; jt < 8; jt++) {
        int cur = jt & 1;
        __syncthreads();
        if (jt + 1 < 8) {
            int j0 = (jt + 1) * 64;
            int row = tid >> 3, off = (tid & 7) << 3;
            const float* src = v + (size_t)(b * SEQ + j0 + row) * Hdim + h * DHEAD + off;
            unsigned d = (unsigned)__cvta_generic_to_shared(&Ks[cur ^ 1][row][off]);
            CPA16(d, src); CPA16(d + 16, src + 4);
        }
        cp_commit();
        asm volatile("cp.async.wait_group 1;");
        __syncthreads();

#pragma unroll
        for (int kg = 0; kg < 8; kg++) {
            int kk = kg * 8;
            int scol = jt * 64 + kk;
            unsigned a0 = __float_as_uint(S[wm + r    ][scol + cq]);
            unsigned a1 = __float_as_uint(S[wm + r + 8][scol + cq]);
            unsigned a2 = __float_as_uint(S[wm + r    ][scol + cq + 4]);
            unsigned a3 = __float_as_uint(S[wm + r + 8][scol + cq + 4]);
#pragma unroll
            for (int nt = 0; nt < 2; nt++) {
                int nn = wn + nt * 8 + r;
                unsigned b0 = __float_as_uint(Ks[cur][kk + cq    ][nn]);
                unsigned b1 = __float_as_uint(Ks[cur][kk + cq + 4][nn]);
                mma8(acco[nt], a0, a1, a2, a3, b0, b1);
            }
        }
    }

    // epilogue: write ctx (tf32-rounded, feeds O-proj)
#pragma unroll
    for (int nt = 0; nt < 2; nt++) {
        int irow = b * SEQ + i0 + wm + r;
        int col = h * DHEAD + wn + nt * 8 + cq * 2;
        *(float2*)&ctx[(size_t)irow * Hdim + col] =
            make_float2(roundtf(acco[nt][0]), roundtf(acco[nt][1]));
        *(float2*)&ctx[(size_t)(irow + 8) * Hdim + col] =
            make_float2(roundtf(acco[nt][2]), roundtf(acco[nt][3]));
    }
}

// ---------------- heads: entity logits + pi/pj for relations ------------------
__global__ __launch_bounds__(256) void heads_kernel(
    const float* __restrict__ x, const float* __restrict__ W_ent,
    const float* __restrict__ b_ent, const float* __restrict__ W_rel,
    const float* __restrict__ b_rel, float* __restrict__ ent_out)
{
    int t = blockIdx.x;
    int tid = threadIdx.x;
    __shared__ float xs[Hdim];
    for (int i = tid; i < Hdim; i += 256) xs[i] = x[(size_t)t * Hdim + i];
    __syncthreads();
    int warp = tid >> 5, lane = tid & 31;
    for (int o = warp; o < NEnt + 2 * NRel; o += 8) {
        float s = 0.f;
        if (o < NEnt) {
            for (int k = lane; k < Hdim; k += 32) s += xs[k] * W_ent[(size_t)k * NEnt + o];
        } else if (o < NEnt + NRel) {
            int rr = o - NEnt;
            for (int k = lane; k < Hdim; k += 32) s += xs[k] * W_rel[(size_t)k * NRel + rr];
        } else {
            int rr = o - NEnt - NRel;
            for (int k = lane; k < Hdim; k += 32) s += xs[k] * W_rel[(size_t)(Hdim + k) * NRel + rr];
        }
#pragma unroll
        for (int off = 16; off; off >>= 1) s += __shfl_xor_sync(0xFFFFFFFFu, s, off);
        if (lane == 0) {
            if (o < NEnt)             ent_out[(size_t)t * NEnt + o] = s + b_ent[o];
            else if (o < NEnt + NRel) g_pi[t * NRel + (o - NEnt)] = s;
            else                      g_pj[t * NRel + (o - NEnt - NRel)] = s + b_rel[o - NEnt - NRel];
        }
    }
}

// ---------------- relation broadcast ------------------------------------------
__global__ __launch_bounds__(256) void relation_kernel(float* __restrict__ out)
{
    int bi = blockIdx.x;
    int b = bi >> 9;
    __shared__ float ps[NRel];
    if (threadIdx.x < NRel) ps[threadIdx.x] = g_pi[bi * NRel + threadIdx.x];
    __syncthreads();
    const float* pjb = g_pj + (size_t)(b << 9) * NRel;
    float* o = out + (size_t)bi * SEQ * NRel;
    for (int idx = threadIdx.x; idx < SEQ * NRel; idx += 256) {
        int r = idx % NRel;
        o[idx] = ps[r] + pjb[idx];
    }
}

// ---------------- host orchestration -----------------------------------------
extern "C" void kernel_launch(void* const* d_in, const int* in_sizes, int n_in,
                              void* d_out, int out_size)
{
    const int*   input_ids = (const int*)  d_in[0];
    const int*   attn_mask = (const int*)  d_in[1];
    const float* emb_word  = (const float*)d_in[2];
    const float* emb_pos   = (const float*)d_in[3];
    const float* emb_type  = (const float*)d_in[4];
    const float* emb_ln_g  = (const float*)d_in[5];
    const float* emb_ln_b  = (const float*)d_in[6];
    const float* Wq = (const float*)d_in[7];
    const float* bq = (const float*)d_in[8];
    const float* Wk = (const float*)d_in[9];
    const float* bk = (const float*)d_in[10];
    const float* Wv = (const float*)d_in[11];
    const float* bv = (const float*)d_in[12];
    const float* Wo = (const float*)d_in[13];
    const float* bo = (const float*)d_in[14];
    const float* ln1_g = (const float*)d_in[15];
    const float* ln1_b = (const float*)d_in[16];
    const float* W1 = (const float*)d_in[17];
    const float* b1 = (const float*)d_in[18];
    const float* W2 = (const float*)d_in[19];
    const float* b2 = (const float*)d_in[20];
    const float* ln2_g = (const float*)d_in[21];
    const float* ln2_b = (const float*)d_in[22];
    const float* W_ent = (const float*)d_in[23];
    const float* b_ent = (const float*)d_in[24];
    const float* W_rel = (const float*)d_in[25];
    const float* b_rel = (const float*)d_in[26];

    float *x, *xr, *q, *k, *v, *ctx, *ffn;
    cudaGetSymbolAddress((void**)&x,   g_x);
    cudaGetSymbolAddress((void**)&xr,  g_xr);
    cudaGetSymbolAddress((void**)&q,   g_q);
    cudaGetSymbolAddress((void**)&k,   g_k);
    cudaGetSymbolAddress((void**)&v,   g_v);
    cudaGetSymbolAddress((void**)&ctx, g_ctx);
    cudaGetSymbolAddress((void**)&ffn, g_ffn);

    cudaFuncSetAttribute(attn_fused_kernel,
                         cudaFuncAttributeMaxDynamicSharedMemorySize, ATTN_SMEM);
    cudaFuncSetAttribute(tf32_gemm_kernel,
                         cudaFuncAttributeMaxDynamicSharedMemorySize, GEMM_SMEM);
    cudaFuncSetAttribute(tf32_gemm64_kernel,
                         cudaFuncAttributeMaxDynamicSharedMemorySize, G64_SMEM);

    embed_ln_kernel<<<MTOK, 256>>>(input_ids, emb_word, emb_pos, emb_type,
                                   emb_ln_g, emb_ln_b);
    abias_kernel<<<(BATCH * SEQ + 255) / 256, 256>>>(attn_mask);

    dim3 gQKV(Hdim / 128, MTOK / 128, 3);
    dim3 gF1(FFdim / 128, MTOK / 128, 1);
    dim3 g64(Hdim / 128, MTOK / 64);          // 6 x 32 = 192 blocks
    dim3 gA(SEQ / 64, BATCH * NHEADS);        // 8 x 48 = 384 blocks

    for (int l = 0; l < NLAY; l++) {
        size_t wHH = (size_t)l * Hdim * Hdim;
        size_t wH  = (size_t)l * Hdim;
        size_t wHF = (size_t)l * Hdim * FFdim;
        tf32_gemm_kernel<<<gQKV, 256, GEMM_SMEM>>>(xr, Wq + wHH, Wk + wHH, Wv + wHH,
                                        bq + wH, bk + wH, bv + wH,
                                        q, k, v, MTOK, Hdim, Hdim, 0, 1);
        attn_fused_kernel<<<gA, 512, ATTN_SMEM>>>(q, k, v, ctx);
        tf32_gemm64_kernel<<<g64, 256, G64_SMEM>>>(ctx, Wo + wHH, bo + wH,
                                                   q, MTOK, Hdim, Hdim, 0, 0);
        add_ln_kernel<<<MTOK, 256>>>(x, q, ln1_g + wH, ln1_b + wH);
        tf32_gemm_kernel<<<gF1, 256, GEMM_SMEM>>>(xr, W1 + wHF, W1 + wHF, W1 + wHF,
                                       b1 + (size_t)l * FFdim, b1 + (size_t)l * FFdim, b1 + (size_t)l * FFdim,
                                       ffn, ffn, ffn, MTOK, FFdim, Hdim, 1, 1);
        tf32_gemm64_kernel<<<g64, 256, G64_SMEM>>>(ffn, W2 + wHF, b2 + wH,
                                                   q, MTOK, Hdim, FFdim, 0, 0);
        add_ln_kernel<<<MTOK, 256>>>(x, q, ln2_g + wH, ln2_b + wH);
    }

    float* out = (float*)d_out;
    heads_kernel<<<MTOK, 256>>>(x, W_ent, b_ent, W_rel, b_rel, out);
    relation_kernel<<<MTOK, 256>>>(out + (size_t)MTOK * NEnt);
}

// round 11
// speedup vs baseline: 1.1763x; 1.1452x over previous
#include <cuda_runtime.h>
#include <math.h>

#define Hdim   768
#define FFdim  3072
#define NLAY   12
#define NHEADS 12
#define DHEAD  64
#define BATCH  4
#define SEQ    512
#define MTOK   (BATCH*SEQ)   // 2048
#define NEnt   12
#define NRel   13
#define NSPLIT 3

// ---------------- scratch (static device globals; no allocation) -------------
__device__ float g_x[MTOK*Hdim];
__device__ float g_xr[MTOK*Hdim];      // tf32-rounded copy of x (GEMM A side)
__device__ float g_q[MTOK*Hdim];
__device__ float g_k[MTOK*Hdim];
__device__ float g_v[MTOK*Hdim];
__device__ float g_ctx[MTOK*Hdim];
__device__ float g_ffn[MTOK*FFdim];
__device__ float g_part[(size_t)NSPLIT*MTOK*Hdim];   // split-K partials
__device__ float g_pi[MTOK*NRel];
__device__ float g_pj[MTOK*NRel];
__device__ float g_abias[BATCH*SEQ];

// ---------------- tf32 helpers ------------------------------------------------
__device__ __forceinline__ unsigned f2tf(float f) {
    unsigned u;
    asm("cvt.rna.tf32.f32 %0, %1;" : "=r"(u) : "f"(f));
    return u;
}
__device__ __forceinline__ float roundtf(float f) { return __uint_as_float(f2tf(f)); }
__device__ __forceinline__ void mma8(float* c, unsigned a0, unsigned a1,
                                     unsigned a2, unsigned a3,
                                     unsigned b0, unsigned b1) {
    asm volatile(
        "mma.sync.aligned.m16n8k8.row.col.f32.tf32.tf32.f32 "
        "{%0,%1,%2,%3},{%4,%5,%6,%7},{%8,%9},{%0,%1,%2,%3};"
        : "+f"(c[0]), "+f"(c[1]), "+f"(c[2]), "+f"(c[3])
        : "r"(a0), "r"(a1), "r"(a2), "r"(a3), "r"(b0), "r"(b1));
}
#define CPA16(dst, src) \
    asm volatile("cp.async.ca.shared.global [%0], [%1], 16;" :: "r"(dst), "l"(src))
__device__ __forceinline__ void cp_commit() { asm volatile("cp.async.commit_group;"); }

// ---------------- embedding + LayerNorm ---------------------------------------
__global__ __launch_bounds__(256) void embed_ln_kernel(
    const int* __restrict__ ids, const float* __restrict__ ew,
    const float* __restrict__ ep, const float* __restrict__ et,
    const float* __restrict__ g, const float* __restrict__ b)
{
    int t = blockIdx.x;
    int s = t & (SEQ - 1);
    int id = ids[t];
    int tid = threadIdx.x;
    float vals[3];
    float sum = 0.f;
#pragma unroll
    for (int i = 0; i < 3; i++) {
        int c = tid + i * 256;
        vals[i] = ew[(size_t)id * Hdim + c] + ep[(size_t)s * Hdim + c] + et[c];
        sum += vals[i];
    }
    __shared__ float red[256];
    red[tid] = sum; __syncthreads();
    for (int o = 128; o; o >>= 1) { if (tid < o) red[tid] += red[tid + o]; __syncthreads(); }
    float mean = red[0] * (1.f / Hdim);
    __syncthreads();
    float sq = 0.f;
#pragma unroll
    for (int i = 0; i < 3; i++) { float d = vals[i] - mean; sq += d * d; }
    red[tid] = sq; __syncthreads();
    for (int o = 128; o; o >>= 1) { if (tid < o) red[tid] += red[tid + o]; __syncthreads(); }
    float rstd = rsqrtf(red[0] * (1.f / Hdim) + 1e-12f);
#pragma unroll
    for (int i = 0; i < 3; i++) {
        int c = tid + i * 256;
        float v = (vals[i] - mean) * rstd * g[c] + b[c];
        g_x [(size_t)t * Hdim + c] = v;
        g_xr[(size_t)t * Hdim + c] = roundtf(v);
    }
}

// ------- split-K reduction + bias + residual add + LayerNorm (in-place x) -----
__global__ __launch_bounds__(256) void reduce3_add_ln_kernel(
    const float* __restrict__ part, const float* __restrict__ bias,
    float* __restrict__ x,
    const float* __restrict__ g, const float* __restrict__ b)
{
    const size_t MN = (size_t)MTOK * Hdim;
    int t = blockIdx.x;
    int tid = threadIdx.x;
    float vals[3];
    float sum = 0.f;
#pragma unroll
    for (int i = 0; i < 3; i++) {
        int c = tid + i * 256;
        size_t idx = (size_t)t * Hdim + c;
        float y = part[idx] + part[MN + idx] + part[2 * MN + idx] + bias[c];
        vals[i] = x[idx] + y;
        sum += vals[i];
    }
    __shared__ float red[256];
    red[tid] = sum; __syncthreads();
    for (int o = 128; o; o >>= 1) { if (tid < o) red[tid] += red[tid + o]; __syncthreads(); }
    float mean = red[0] * (1.f / Hdim);
    __syncthreads();
    float sq = 0.f;
#pragma unroll
    for (int i = 0; i < 3; i++) { float d = vals[i] - mean; sq += d * d; }
    red[tid] = sq; __syncthreads();
    for (int o = 128; o; o >>= 1) { if (tid < o) red[tid] += red[tid + o]; __syncthreads(); }
    float rstd = rsqrtf(red[0] * (1.f / Hdim) + 1e-12f);
#pragma unroll
    for (int i = 0; i < 3; i++) {
        int c = tid + i * 256;
        float v = (vals[i] - mean) * rstd * g[c] + b[c];
        x[(size_t)t * Hdim + c] = v;
        g_xr[(size_t)t * Hdim + c] = roundtf(v);
    }
}

// ---------------- tf32 GEMM: BM=128 BN=128 BK=16, 256 thr, 4-stage ------------
#define GEMM_STAGES 4
#define GEMM_SMEM   (GEMM_STAGES * (128*20 + 16*136) * 4)   // 75776 bytes
__global__ __launch_bounds__(256, 2) void tf32_gemm_kernel(
    const float* __restrict__ A,
    const float* __restrict__ W0, const float* __restrict__ W1, const float* __restrict__ W2,
    const float* __restrict__ bias0, const float* __restrict__ bias1, const float* __restrict__ bias2,
    float* __restrict__ C0, float* __restrict__ C1, float* __restrict__ C2,
    int M, int N, int K, int act, int rnd)
{
    int z = blockIdx.z;
    const float* W    = (z == 0) ? W0    : (z == 1) ? W1    : W2;
    const float* bias = (z == 0) ? bias0 : (z == 1) ? bias1 : bias2;
    float*       C    = (z == 0) ? C0    : (z == 1) ? C1    : C2;

    extern __shared__ float smem[];
    float (*As)[128][20]  = (float(*)[128][20])smem;
    float (*Bs)[16][136]  = (float(*)[16][136])(smem + GEMM_STAGES*128*20);

    int tid = threadIdx.x;
    int warp = tid >> 5, lane = tid & 31;
    int r = lane >> 2, cq = lane & 3;
    int wm = (warp >> 2) * 64;
    int wn = (warp & 3) * 32;
    int m0 = blockIdx.y * 128, n0 = blockIdx.x * 128;

    float acc[4][4][4];
#pragma unroll
    for (int i = 0; i < 4; i++)
#pragma unroll
        for (int j = 0; j < 4; j++)
#pragma unroll
            for (int t = 0; t < 4; t++) acc[i][j][t] = 0.f;

    int KT = K / 16;

#pragma unroll
    for (int s = 0; s < GEMM_STAGES - 1; s++) {
        int k0 = s * 16;
#pragma unroll
        for (int u = 0; u < 2; u++) {
            int f = tid + u * 256;
            int row = f >> 2, seg = (f & 3) * 4;
            unsigned da = (unsigned)__cvta_generic_to_shared(&As[s][row][seg]);
            CPA16(da, A + (size_t)(m0 + row) * K + k0 + seg);
        }
#pragma unroll
        for (int u = 0; u < 2; u++) {
            int f = tid + u * 256;
            int row = f >> 5, off = (f & 31) * 4;
            unsigned db = (unsigned)__cvta_generic_to_shared(&Bs[s][row][off]);
            CPA16(db, W + (size_t)(k0 + row) * N + n0 + off);
        }
        cp_commit();
    }

    for (int kt = 0; kt < KT; kt++) {
        int cur = kt & (GEMM_STAGES - 1);
        asm volatile("cp.async.wait_group %0;" :: "n"(GEMM_STAGES - 2));
        __syncthreads();

        if (kt + GEMM_STAGES - 1 < KT) {
            int s = (kt + GEMM_STAGES - 1) & (GEMM_STAGES - 1);
            int k0 = (kt + GEMM_STAGES - 1) * 16;
#pragma unroll
            for (int u = 0; u < 2; u++) {
                int f = tid + u * 256;
                int row = f >> 2, seg = (f & 3) * 4;
                unsigned da = (unsigned)__cvta_generic_to_shared(&As[s][row][seg]);
                CPA16(da, A + (size_t)(m0 + row) * K + k0 + seg);
            }
#pragma unroll
            for (int u = 0; u < 2; u++) {
                int f = tid + u * 256;
                int row = f >> 5, off = (f & 31) * 4;
                unsigned db = (unsigned)__cvta_generic_to_shared(&Bs[s][row][off]);
                CPA16(db, W + (size_t)(k0 + row) * N + n0 + off);
            }
        }
        cp_commit();

#pragma unroll
        for (int ks = 0; ks < 2; ks++) {
            int kk = ks * 8;
            unsigned af[4][4], bf[4][2];
#pragma unroll
            for (int mt = 0; mt < 4; mt++) {
                int mr = wm + mt * 16 + r;
                af[mt][0] = __float_as_uint(As[cur][mr    ][kk + cq]);
                af[mt][1] = __float_as_uint(As[cur][mr + 8][kk + cq]);
                af[mt][2] = __float_as_uint(As[cur][mr    ][kk + cq + 4]);
                af[mt][3] = __float_as_uint(As[cur][mr + 8][kk + cq + 4]);
            }
#pragma unroll
            for (int nt = 0; nt < 4; nt++) {
                int nn = wn + nt * 8 + r;
                bf[nt][0] = f2tf(Bs[cur][kk + cq    ][nn]);
                bf[nt][1] = f2tf(Bs[cur][kk + cq + 4][nn]);
            }
#pragma unroll
            for (int mt = 0; mt < 4; mt++)
#pragma unroll
                for (int nt = 0; nt < 4; nt++)
                    mma8(acc[mt][nt], af[mt][0], af[mt][1], af[mt][2], af[mt][3],
                         bf[nt][0], bf[nt][1]);
        }
    }

#pragma unroll
    for (int mt = 0; mt < 4; mt++) {
        int row = m0 + wm + mt * 16 + r;
#pragma unroll
        for (int nt = 0; nt < 4; nt++) {
            int col = n0 + wn + nt * 8 + cq * 2;
            float2 bb = *(const float2*)&bias[col];
            float v0 = acc[mt][nt][0] + bb.x;
            float v1 = acc[mt][nt][1] + bb.y;
            float v2 = acc[mt][nt][2] + bb.x;
            float v3 = acc[mt][nt][3] + bb.y;
            if (act) {
                v0 = 0.5f * v0 * (1.0f + erff(v0 * 0.70710678118654752f));
                v1 = 0.5f * v1 * (1.0f + erff(v1 * 0.70710678118654752f));
                v2 = 0.5f * v2 * (1.0f + erff(v2 * 0.70710678118654752f));
                v3 = 0.5f * v3 * (1.0f + erff(v3 * 0.70710678118654752f));
            }
            if (rnd) {
                v0 = roundtf(v0); v1 = roundtf(v1);
                v2 = roundtf(v2); v3 = roundtf(v3);
            }
            *(float2*)&C[(size_t)row * N + col]       = make_float2(v0, v1);
            *(float2*)&C[(size_t)(row + 8) * N + col] = make_float2(v2, v3);
        }
    }
}

// ------- tf32 GEMM split-K: BM=64 BN=128 BK=16, 256 thr, 4-stage --------------
// grid (N/128, M/64, NSPLIT); block z computes K slice [z*Ks, (z+1)*Ks),
// writes raw partials (no bias/act) to Cpart + z*M*N.
#define G64_STAGES 4
#define G64_SMEM   (G64_STAGES * (64*20 + 16*136) * 4)   // 55296 bytes
__global__ __launch_bounds__(256, 2) void tf32_gemm64_splitk_kernel(
    const float* __restrict__ A, const float* __restrict__ W,
    float* __restrict__ Cpart, int M, int N, int K, int Ks)
{
    extern __shared__ float smem[];
    float (*As)[64][20]  = (float(*)[64][20])smem;
    float (*Bs)[16][136] = (float(*)[16][136])(smem + G64_STAGES*64*20);

    int tid = threadIdx.x;
    int warp = tid >> 5, lane = tid & 31;
    int r = lane >> 2, cq = lane & 3;
    int wm = (warp >> 2) * 32;
    int wn = (warp & 3) * 32;
    int m0 = blockIdx.y * 64, n0 = blockIdx.x * 128;
    int kbase = blockIdx.z * Ks;
    float* C = Cpart + (size_t)blockIdx.z * M * N;

    float acc[2][4][4];
#pragma unroll
    for (int i = 0; i < 2; i++)
#pragma unroll
        for (int j = 0; j < 4; j++)
#pragma unroll
            for (int t = 0; t < 4; t++) acc[i][j][t] = 0.f;

    int KT = Ks / 16;

#pragma unroll
    for (int s = 0; s < G64_STAGES - 1; s++) {
        int k0 = kbase + s * 16;
        {
            int row = tid >> 2, seg = (tid & 3) * 4;
            unsigned da = (unsigned)__cvta_generic_to_shared(&As[s][row][seg]);
            CPA16(da, A + (size_t)(m0 + row) * K + k0 + seg);
        }
#pragma unroll
        for (int u = 0; u < 2; u++) {
            int f = tid + u * 256;
            int row = f >> 5, off = (f & 31) * 4;
            unsigned db = (unsigned)__cvta_generic_to_shared(&Bs[s][row][off]);
            CPA16(db, W + (size_t)(k0 + row) * N + n0 + off);
        }
        cp_commit();
    }

    for (int kt = 0; kt < KT; kt++) {
        int cur = kt & (G64_STAGES - 1);
        asm volatile("cp.async.wait_group %0;" :: "n"(G64_STAGES - 2));
        __syncthreads();

        if (kt + G64_STAGES - 1 < KT) {
            int s = (kt + G64_STAGES - 1) & (G64_STAGES - 1);
            int k0 = kbase + (kt + G64_STAGES - 1) * 16;
            {
                int row = tid >> 2, seg = (tid & 3) * 4;
                unsigned da = (unsigned)__cvta_generic_to_shared(&As[s][row][seg]);
                CPA16(da, A + (size_t)(m0 + row) * K + k0 + seg);
            }
#pragma unroll
            for (int u = 0; u < 2; u++) {
                int f = tid + u * 256;
                int row = f >> 5, off = (f & 31) * 4;
                unsigned db = (unsigned)__cvta_generic_to_shared(&Bs[s][row][off]);
                CPA16(db, W + (size_t)(k0 + row) * N + n0 + off);
            }
        }
        cp_commit();

#pragma unroll
        for (int ks = 0; ks < 2; ks++) {
            int kk = ks * 8;
            unsigned af[2][4], bf[4][2];
#pragma unroll
            for (int mt = 0; mt < 2; mt++) {
                int mr = wm + mt * 16 + r;
                af[mt][0] = __float_as_uint(As[cur][mr    ][kk + cq]);
                af[mt][1] = __float_as_uint(As[cur][mr + 8][kk + cq]);
                af[mt][2] = __float_as_uint(As[cur][mr    ][kk + cq + 4]);
                af[mt][3] = __float_as_uint(As[cur][mr + 8][kk + cq + 4]);
            }
#pragma unroll
            for (int nt = 0; nt < 4; nt++) {
                int nn = wn + nt * 8 + r;
                bf[nt][0] = f2tf(Bs[cur][kk + cq    ][nn]);
                bf[nt][1] = f2tf(Bs[cur][kk + cq + 4][nn]);
            }
#pragma unroll
            for (int mt = 0; mt < 2; mt++)
#pragma unroll
                for (int nt = 0; nt < 4; nt++)
                    mma8(acc[mt][nt], af[mt][0], af[mt][1], af[mt][2], af[mt][3],
                         bf[nt][0], bf[nt][1]);
        }
    }

#pragma unroll
    for (int mt = 0; mt < 2; mt++) {
        int row = m0 + wm + mt * 16 + r;
#pragma unroll
        for (int nt = 0; nt < 4; nt++) {
            int col = n0 + wn + nt * 8 + cq * 2;
            *(float2*)&C[(size_t)row * N + col] =
                make_float2(acc[mt][nt][0], acc[mt][nt][1]);
            *(float2*)&C[(size_t)(row + 8) * N + col] =
                make_float2(acc[mt][nt][2], acc[mt][nt][3]);
        }
    }
}

// ---------------- attention-mask bias -----------------------------------------
__global__ void abias_kernel(const int* __restrict__ mask)
{
    int i = blockIdx.x * blockDim.x + threadIdx.x;
    if (i < BATCH * SEQ) g_abias[i] = (1.f - (float)mask[i]) * -10000.f;
}

// ---------------- fused attention: scores + softmax + P@V (round-8 best) ------
#define ATTN_SMEM ((64*68 + 2*64*68 + 64*516) * 4)   // 184320 bytes
__global__ __launch_bounds__(256) void attn_fused_kernel(
    const float* __restrict__ q, const float* __restrict__ k,
    const float* __restrict__ v, float* __restrict__ ctx)
{
    extern __shared__ float sm[];
    float (*Qs)[68]     = (float(*)[68])sm;                     // 64x68
    float (*Ks)[64][68] = (float(*)[64][68])(sm + 64*68);       // [2][64][68] (K, then V)
    float (*S)[516]     = (float(*)[516])(sm + 3*64*68);        // 64x516

    int bh = blockIdx.y;
    int b = bh / NHEADS, h = bh - b * NHEADS;
    int i0 = blockIdx.x * 64;
    int tid = threadIdx.x;
    int warp = tid >> 5, lane = tid & 31;
    int r = lane >> 2, cq = lane & 3;
    int wm = (warp >> 2) * 32;      // scores phase: 2 m-warps
    int wn = (warp & 3) * 16;       // scores phase: 4 n-warps

    // load Q tile
#pragma unroll
    for (int u = 0; u < 2; u++) {
        int c = tid + u * 256;
        int row = c >> 3, off = (c & 7) << 3;
        float4 v0 = *(const float4*)(q + (size_t)(b * SEQ + i0 + row) * Hdim + h * DHEAD + off);
        float4 v1 = *(const float4*)(q + (size_t)(b * SEQ + i0 + row) * Hdim + h * DHEAD + off + 4);
        *(float4*)&Qs[row][off]     = v0;
        *(float4*)&Qs[row][off + 4] = v1;
    }
    __syncthreads();

    // Q fragments in registers
    unsigned aq[8][2][4];
#pragma unroll
    for (int ks = 0; ks < 8; ks++) {
        int kk = ks * 8;
#pragma unroll
        for (int mt = 0; mt < 2; mt++) {
            int mr = wm + mt * 16 + r;
            aq[ks][mt][0] = __float_as_uint(Qs[mr    ][kk + cq]);
            aq[ks][mt][1] = __float_as_uint(Qs[mr + 8][kk + cq]);
            aq[ks][mt][2] = __float_as_uint(Qs[mr    ][kk + cq + 4]);
            aq[ks][mt][3] = __float_as_uint(Qs[mr + 8][kk + cq + 4]);
        }
    }

    // prologue K tile 0
#pragma unroll
    for (int u = 0; u < 2; u++) {
        int c = tid + u * 256;
        int row = c >> 3, off = (c & 7) << 3;
        const float* src = k + (size_t)(b * SEQ + row) * Hdim + h * DHEAD + off;
        unsigned d = (unsigned)__cvta_generic_to_shared(&Ks[0][row][off]);
        CPA16(d, src); CPA16(d + 16, src + 4);
    }
    cp_commit();

    // ---- scores phase ----
    for (int jt = 0; jt < 8; jt++) {
        int cur = jt & 1;
        __syncthreads();
        if (jt + 1 < 8) {
            int j0 = (jt + 1) * 64;
#pragma unroll
            for (int u = 0; u < 2; u++) {
                int c = tid + u * 256;
                int row = c >> 3, off = (c & 7) << 3;
                const float* src = k + (size_t)(b * SEQ + j0 + row) * Hdim + h * DHEAD + off;
                unsigned d = (unsigned)__cvta_generic_to_shared(&Ks[cur ^ 1][row][off]);
                CPA16(d, src); CPA16(d + 16, src + 4);
            }
        }
        cp_commit();
        asm volatile("cp.async.wait_group 1;");
        __syncthreads();

        float acc[2][2][4];
#pragma unroll
        for (int i = 0; i < 2; i++)
#pragma unroll
            for (int j = 0; j < 2; j++)
#pragma unroll
                for (int t = 0; t < 4; t++) acc[i][j][t] = 0.f;

#pragma unroll
        for (int ks = 0; ks < 8; ks++) {
            int kk = ks * 8;
            unsigned bf[2][2];
#pragma unroll
            for (int nt = 0; nt < 2; nt++) {
                int nn = wn + nt * 8 + r;
                bf[nt][0] = __float_as_uint(Ks[cur][nn][kk + cq]);
                bf[nt][1] = __float_as_uint(Ks[cur][nn][kk + cq + 4]);
            }
#pragma unroll
            for (int mt = 0; mt < 2; mt++)
#pragma unroll
                for (int nt = 0; nt < 2; nt++)
                    mma8(acc[mt][nt], aq[ks][mt][0], aq[ks][mt][1],
                         aq[ks][mt][2], aq[ks][mt][3], bf[nt][0], bf[nt][1]);
        }

#pragma unroll
        for (int mt = 0; mt < 2; mt++) {
            int row = wm + mt * 16 + r;
#pragma unroll
            for (int nt = 0; nt < 2; nt++) {
                int jcol = jt * 64 + wn + nt * 8 + cq * 2;
                float2 ab = *(const float2*)&g_abias[b * SEQ + jcol];
                *(float2*)&S[row][jcol] =
                    make_float2(acc[mt][nt][0] * 0.125f + ab.x,
                                acc[mt][nt][1] * 0.125f + ab.y);
                *(float2*)&S[row + 8][jcol] =
                    make_float2(acc[mt][nt][2] * 0.125f + ab.x,
                                acc[mt][nt][3] * 0.125f + ab.y);
            }
        }
    }

    // prefetch V tile 0 (hidden under softmax)
#pragma unroll
    for (int u = 0; u < 2; u++) {
        int c = tid + u * 256;
        int row = c >> 3, off = (c & 7) << 3;
        const float* src = v + (size_t)(b * SEQ + row) * Hdim + h * DHEAD + off;
        unsigned d = (unsigned)__cvta_generic_to_shared(&Ks[0][row][off]);
        CPA16(d, src); CPA16(d + 16, src + 4);
    }
    cp_commit();
    __syncthreads();

    // ---- softmax (probabilities stay in smem, tf32-rounded) ----
#pragma unroll
    for (int rr = 0; rr < 8; rr++) {
        int row = warp * 8 + rr;
        float vals[16];
        float m = -1e30f;
#pragma unroll
        for (int t = 0; t < 16; t++) {
            vals[t] = S[row][lane + t * 32];
            m = fmaxf(m, vals[t]);
        }
#pragma unroll
        for (int off = 16; off; off >>= 1) m = fmaxf(m, __shfl_xor_sync(0xFFFFFFFFu, m, off));
        float s = 0.f;
#pragma unroll
        for (int t = 0; t < 16; t++) { vals[t] = expf(vals[t] - m); s += vals[t]; }
#pragma unroll
        for (int off = 16; off; off >>= 1) s += __shfl_xor_sync(0xFFFFFFFFu, s, off);
        float inv = 1.f / s;
#pragma unroll
        for (int t = 0; t < 16; t++)
            S[row][lane + t * 32] = roundtf(vals[t] * inv);
    }

    // ---- P@V phase: O(64x64) = S(64x512) @ V(512x64) ----
    int wmv = (warp >> 1) * 16;     // 4 m-warps
    int wnv = (warp & 1) * 32;      // 2 n-warps
    float acco[4][4];
#pragma unroll
    for (int j = 0; j < 4; j++)
#pragma unroll
        for (int t = 0; t < 4; t++) acco[j][t] = 0.f;

    for (int jt = 0; jt < 8; jt++) {
        int cur = jt & 1;
        __syncthreads();
        if (jt + 1 < 8) {
            int j0 = (jt + 1) * 64;
#pragma unroll
            for (int u = 0; u < 2; u++) {
                int c = tid + u * 256;
                int row = c >> 3, off = (c & 7) << 3;
                const float* src = v + (size_t)(b * SEQ + j0 + row) * Hdim + h * DHEAD + off;
                unsigned d = (unsigned)__cvta_generic_to_shared(&Ks[cur ^ 1][row][off]);
                CPA16(d, src); CPA16(d + 16, src + 4);
            }
        }
        cp_commit();
        asm volatile("cp.async.wait_group 1;");
        __syncthreads();

#pragma unroll
        for (int kg = 0; kg < 8; kg++) {
            int kk = kg * 8;
            int scol = jt * 64 + kk;
            unsigned a0 = __float_as_uint(S[wmv + r    ][scol + cq]);
            unsigned a1 = __float_as_uint(S[wmv + r + 8][scol + cq]);
            unsigned a2 = __float_as_uint(S[wmv + r    ][scol + cq + 4]);
            unsigned a3 = __float_as_uint(S[wmv + r + 8][scol + cq + 4]);
#pragma unroll
            for (int nt = 0; nt < 4; nt++) {
                int nn = wnv + nt * 8 + r;
                unsigned b0 = __float_as_uint(Ks[cur][kk + cq    ][nn]);
                unsigned b1 = __float_as_uint(Ks[cur][kk + cq + 4][nn]);
                mma8(acco[nt], a0, a1, a2, a3, b0, b1);
            }
        }
    }

    // epilogue: write ctx (tf32-rounded, feeds O-proj)
#pragma unroll
    for (int nt = 0; nt < 4; nt++) {
        int irow = b * SEQ + i0 + wmv + r;
        int col = h * DHEAD + wnv + nt * 8 + cq * 2;
        *(float2*)&ctx[(size_t)irow * Hdim + col] =
            make_float2(roundtf(acco[nt][0]), roundtf(acco[nt][1]));
        *(float2*)&ctx[(size_t)(irow + 8) * Hdim + col] =
            make_float2(roundtf(acco[nt][2]), roundtf(acco[nt][3]));
    }
}

// ---------------- heads: entity logits + pi/pj for relations ------------------
__global__ __launch_bounds__(256) void heads_kernel(
    const float* __restrict__ x, const float* __restrict__ W_ent,
    const float* __restrict__ b_ent, const float* __restrict__ W_rel,
    const float* __restrict__ b_rel, float* __restrict__ ent_out)
{
    int t = blockIdx.x;
    int tid = threadIdx.x;
    __shared__ float xs[Hdim];
    for (int i = tid; i < Hdim; i += 256) xs[i] = x[(size_t)t * Hdim + i];
    __syncthreads();
    int warp = tid >> 5, lane = tid & 31;
    for (int o = warp; o < NEnt + 2 * NRel; o += 8) {
        float s = 0.f;
        if (o < NEnt) {
            for (int k = lane; k < Hdim; k += 32) s += xs[k] * W_ent[(size_t)k * NEnt + o];
        } else if (o < NEnt + NRel) {
            int rr = o - NEnt;
            for (int k = lane; k < Hdim; k += 32) s += xs[k] * W_rel[(size_t)k * NRel + rr];
        } else {
            int rr = o - NEnt - NRel;
            for (int k = lane; k < Hdim; k += 32) s += xs[k] * W_rel[(size_t)(Hdim + k) * NRel + rr];
        }
#pragma unroll
        for (int off = 16; off; off >>= 1) s += __shfl_xor_sync(0xFFFFFFFFu, s, off);
        if (lane == 0) {
            if (o < NEnt)             ent_out[(size_t)t * NEnt + o] = s + b_ent[o];
            else if (o < NEnt + NRel) g_pi[t * NRel + (o - NEnt)] = s;
            else                      g_pj[t * NRel + (o - NEnt - NRel)] = s + b_rel[o - NEnt - NRel];
        }
    }
}

// ---------------- relation broadcast ------------------------------------------
__global__ __launch_bounds__(256) void relation_kernel(float* __restrict__ out)
{
    int bi = blockIdx.x;
    int b = bi >> 9;
    __shared__ float ps[NRel];
    if (threadIdx.x < NRel) ps[threadIdx.x] = g_pi[bi * NRel + threadIdx.x];
    __syncthreads();
    const float* pjb = g_pj + (size_t)(b << 9) * NRel;
    float* o = out + (size_t)bi * SEQ * NRel;
    for (int idx = threadIdx.x; idx < SEQ * NRel; idx += 256) {
        int r = idx % NRel;
        o[idx] = ps[r] + pjb[idx];
    }
}

// ---------------- host orchestration -----------------------------------------
extern "C" void kernel_launch(void* const* d_in, const int* in_sizes, int n_in,
                              void* d_out, int out_size)
{
    const int*   input_ids = (const int*)  d_in[0];
    const int*   attn_mask = (const int*)  d_in[1];
    const float* emb_word  = (const float*)d_in[2];
    const float* emb_pos   = (const float*)d_in[3];
    const float* emb_type  = (const float*)d_in[4];
    const float* emb_ln_g  = (const float*)d_in[5];
    const float* emb_ln_b  = (const float*)d_in[6];
    const float* Wq = (const float*)d_in[7];
    const float* bq = (const float*)d_in[8];
    const float* Wk = (const float*)d_in[9];
    const float* bk = (const float*)d_in[10];
    const float* Wv = (const float*)d_in[11];
    const float* bv = (const float*)d_in[12];
    const float* Wo = (const float*)d_in[13];
    const float* bo = (const float*)d_in[14];
    const float* ln1_g = (const float*)d_in[15];
    const float* ln1_b = (const float*)d_in[16];
    const float* W1 = (const float*)d_in[17];
    const float* b1 = (const float*)d_in[18];
    const float* W2 = (const float*)d_in[19];
    const float* b2 = (const float*)d_in[20];
    const float* ln2_g = (const float*)d_in[21];
    const float* ln2_b = (const float*)d_in[22];
    const float* W_ent = (const float*)d_in[23];
    const float* b_ent = (const float*)d_in[24];
    const float* W_rel = (const float*)d_in[25];
    const float* b_rel = (const float*)d_in[26];

    float *x, *xr, *q, *k, *v, *ctx, *ffn, *part;
    cudaGetSymbolAddress((void**)&x,    g_x);
    cudaGetSymbolAddress((void**)&xr,   g_xr);
    cudaGetSymbolAddress((void**)&q,    g_q);
    cudaGetSymbolAddress((void**)&k,    g_k);
    cudaGetSymbolAddress((void**)&v,    g_v);
    cudaGetSymbolAddress((void**)&ctx,  g_ctx);
    cudaGetSymbolAddress((void**)&ffn,  g_ffn);
    cudaGetSymbolAddress((void**)&part, g_part);

    cudaFuncSetAttribute(attn_fused_kernel,
                         cudaFuncAttributeMaxDynamicSharedMemorySize, ATTN_SMEM);
    cudaFuncSetAttribute(tf32_gemm_kernel,
                         cudaFuncAttributeMaxDynamicSharedMemorySize, GEMM_SMEM);
    cudaFuncSetAttribute(tf32_gemm64_splitk_kernel,
                         cudaFuncAttributeMaxDynamicSharedMemorySize, G64_SMEM);

    embed_ln_kernel<<<MTOK, 256>>>(input_ids, emb_word, emb_pos, emb_type,
                                   emb_ln_g, emb_ln_b);
    abias_kernel<<<(BATCH * SEQ + 255) / 256, 256>>>(attn_mask);

    dim3 gQKV(Hdim / 128, MTOK / 128, 3);
    dim3 gF1(FFdim / 128, MTOK / 128, 1);
    dim3 gSK(Hdim / 128, MTOK / 64, NSPLIT);  // 6 x 32 x 3 = 576 blocks
    dim3 gA(SEQ / 64, BATCH * NHEADS);        // 8 x 48 = 384 blocks

    for (int l = 0; l < NLAY; l++) {
        size_t wHH = (size_t)l * Hdim * Hdim;
        size_t wH  = (size_t)l * Hdim;
        size_t wHF = (size_t)l * Hdim * FFdim;
        tf32_gemm_kernel<<<gQKV, 256, GEMM_SMEM>>>(xr, Wq + wHH, Wk + wHH, Wv + wHH,
                                        bq + wH, bk + wH, bv + wH,
                                        q, k, v, MTOK, Hdim, Hdim, 0, 1);
        attn_fused_kernel<<<gA, 256, ATTN_SMEM>>>(q, k, v, ctx);
        tf32_gemm64_splitk_kernel<<<gSK, 256, G64_SMEM>>>(ctx, Wo + wHH, part,
                                                          MTOK, Hdim, Hdim, Hdim / NSPLIT);
        reduce3_add_ln_kernel<<<MTOK, 256>>>(part, bo + wH, x, ln1_g + wH, ln1_b + wH);
        tf32_gemm_kernel<<<gF1, 256, GEMM_SMEM>>>(xr, W1 + wHF, W1 + wHF, W1 + wHF,
                                       b1 + (size_t)l * FFdim, b1 + (size_t)l * FFdim, b1 + (size_t)l * FFdim,
                                       ffn, ffn, ffn, MTOK, FFdim, Hdim, 1, 1);
        tf32_gemm64_splitk_kernel<<<gSK, 256, G64_SMEM>>>(ffn, W2 + wHF, part,
                                                          MTOK, Hdim, FFdim, FFdim / NSPLIT);
        reduce3_add_ln_kernel<<<MTOK, 256>>>(part, b2 + wH, x, ln2_g + wH, ln2_b + wH);
    }

    float* out = (float*)d_out;
    heads_kernel<<<MTOK, 256>>>(x, W_ent, b_ent, W_rel, b_rel, out);
    relation_kernel<<<MTOK, 256>>>(out + (size_t)MTOK * NEnt);
}

// round 12
// speedup vs baseline: 1.1954x; 1.0162x over previous
#include <cuda_runtime.h>
#include <math.h>

#define Hdim   768
#define FFdim  3072
#define NLAY   12
#define NHEADS 12
#define DHEAD  64
#define BATCH  4
#define SEQ    512
#define MTOK   (BATCH*SEQ)   // 2048
#define NEnt   12
#define NRel   13
#define NSPLIT 3

// ---------------- scratch (static device globals; no allocation) -------------
__device__ float g_x[MTOK*Hdim];
__device__ float g_xr[MTOK*Hdim];      // tf32-rounded copy of x (GEMM A side)
__device__ float g_q[MTOK*Hdim];
__device__ float g_k[MTOK*Hdim];
__device__ float g_v[MTOK*Hdim];
__device__ float g_ctx[MTOK*Hdim];
__device__ float g_ffn[MTOK*FFdim];
__device__ float g_part[(size_t)NSPLIT*MTOK*Hdim];   // split-K partials
__device__ float g_pi[MTOK*NRel];
__device__ float g_pj[MTOK*NRel];
__device__ float g_abias[BATCH*SEQ];

// ---------------- tf32 helpers ------------------------------------------------
__device__ __forceinline__ unsigned f2tf(float f) {
    unsigned u;
    asm("cvt.rna.tf32.f32 %0, %1;" : "=r"(u) : "f"(f));
    return u;
}
__device__ __forceinline__ float roundtf(float f) { return __uint_as_float(f2tf(f)); }
__device__ __forceinline__ void mma8(float* c, unsigned a0, unsigned a1,
                                     unsigned a2, unsigned a3,
                                     unsigned b0, unsigned b1) {
    asm volatile(
        "mma.sync.aligned.m16n8k8.row.col.f32.tf32.tf32.f32 "
        "{%0,%1,%2,%3},{%4,%5,%6,%7},{%8,%9},{%0,%1,%2,%3};"
        : "+f"(c[0]), "+f"(c[1]), "+f"(c[2]), "+f"(c[3])
        : "r"(a0), "r"(a1), "r"(a2), "r"(a3), "r"(b0), "r"(b1));
}
#define CPA16(dst, src) \
    asm volatile("cp.async.ca.shared.global [%0], [%1], 16;" :: "r"(dst), "l"(src))
__device__ __forceinline__ void cp_commit() { asm volatile("cp.async.commit_group;"); }

// ---------------- embedding + LayerNorm ---------------------------------------
__global__ __launch_bounds__(256) void embed_ln_kernel(
    const int* __restrict__ ids, const float* __restrict__ ew,
    const float* __restrict__ ep, const float* __restrict__ et,
    const float* __restrict__ g, const float* __restrict__ b)
{
    int t = blockIdx.x;
    int s = t & (SEQ - 1);
    int id = ids[t];
    int tid = threadIdx.x;
    float vals[3];
    float sum = 0.f;
#pragma unroll
    for (int i = 0; i < 3; i++) {
        int c = tid + i * 256;
        vals[i] = ew[(size_t)id * Hdim + c] + ep[(size_t)s * Hdim + c] + et[c];
        sum += vals[i];
    }
    __shared__ float red[256];
    red[tid] = sum; __syncthreads();
    for (int o = 128; o; o >>= 1) { if (tid < o) red[tid] += red[tid + o]; __syncthreads(); }
    float mean = red[0] * (1.f / Hdim);
    __syncthreads();
    float sq = 0.f;
#pragma unroll
    for (int i = 0; i < 3; i++) { float d = vals[i] - mean; sq += d * d; }
    red[tid] = sq; __syncthreads();
    for (int o = 128; o; o >>= 1) { if (tid < o) red[tid] += red[tid + o]; __syncthreads(); }
    float rstd = rsqrtf(red[0] * (1.f / Hdim) + 1e-12f);
#pragma unroll
    for (int i = 0; i < 3; i++) {
        int c = tid + i * 256;
        float v = (vals[i] - mean) * rstd * g[c] + b[c];
        g_x [(size_t)t * Hdim + c] = v;
        g_xr[(size_t)t * Hdim + c] = roundtf(v);
    }
}

// ------- split-K reduction + bias + residual add + LayerNorm (in-place x) -----
__global__ __launch_bounds__(256) void reduce3_add_ln_kernel(
    const float* __restrict__ part, const float* __restrict__ bias,
    float* __restrict__ x,
    const float* __restrict__ g, const float* __restrict__ b)
{
    const size_t MN = (size_t)MTOK * Hdim;
    int t = blockIdx.x;
    int tid = threadIdx.x;
    float vals[3];
    float sum = 0.f;
#pragma unroll
    for (int i = 0; i < 3; i++) {
        int c = tid + i * 256;
        size_t idx = (size_t)t * Hdim + c;
        float y = part[idx] + part[MN + idx] + part[2 * MN + idx] + bias[c];
        vals[i] = x[idx] + y;
        sum += vals[i];
    }
    __shared__ float red[256];
    red[tid] = sum; __syncthreads();
    for (int o = 128; o; o >>= 1) { if (tid < o) red[tid] += red[tid + o]; __syncthreads(); }
    float mean = red[0] * (1.f / Hdim);
    __syncthreads();
    float sq = 0.f;
#pragma unroll
    for (int i = 0; i < 3; i++) { float d = vals[i] - mean; sq += d * d; }
    red[tid] = sq; __syncthreads();
    for (int o = 128; o; o >>= 1) { if (tid < o) red[tid] += red[tid + o]; __syncthreads(); }
    float rstd = rsqrtf(red[0] * (1.f / Hdim) + 1e-12f);
#pragma unroll
    for (int i = 0; i < 3; i++) {
        int c = tid + i * 256;
        float v = (vals[i] - mean) * rstd * g[c] + b[c];
        x[(size_t)t * Hdim + c] = v;
        g_xr[(size_t)t * Hdim + c] = roundtf(v);
    }
}

// ---------------- tf32 GEMM: BM=128 BN=128 BK=16, 256 thr, 4-stage ------------
#define GEMM_STAGES 4
#define GEMM_SMEM   (GEMM_STAGES * (128*20 + 16*136) * 4)   // 75776 bytes
__global__ __launch_bounds__(256, 2) void tf32_gemm_kernel(
    const float* __restrict__ A,
    const float* __restrict__ W0, const float* __restrict__ W1, const float* __restrict__ W2,
    const float* __restrict__ bias0, const float* __restrict__ bias1, const float* __restrict__ bias2,
    float* __restrict__ C0, float* __restrict__ C1, float* __restrict__ C2,
    int M, int N, int K, int act, int rnd)
{
    int z = blockIdx.z;
    const float* W    = (z == 0) ? W0    : (z == 1) ? W1    : W2;
    const float* bias = (z == 0) ? bias0 : (z == 1) ? bias1 : bias2;
    float*       C    = (z == 0) ? C0    : (z == 1) ? C1    : C2;

    extern __shared__ float smem[];
    float (*As)[128][20]  = (float(*)[128][20])smem;
    float (*Bs)[16][136]  = (float(*)[16][136])(smem + GEMM_STAGES*128*20);

    int tid = threadIdx.x;
    int warp = tid >> 5, lane = tid & 31;
    int r = lane >> 2, cq = lane & 3;
    int wm = (warp >> 2) * 64;
    int wn = (warp & 3) * 32;
    int m0 = blockIdx.y * 128, n0 = blockIdx.x * 128;

    float acc[4][4][4];
#pragma unroll
    for (int i = 0; i < 4; i++)
#pragma unroll
        for (int j = 0; j < 4; j++)
#pragma unroll
            for (int t = 0; t < 4; t++) acc[i][j][t] = 0.f;

    int KT = K / 16;

#pragma unroll
    for (int s = 0; s < GEMM_STAGES - 1; s++) {
        int k0 = s * 16;
#pragma unroll
        for (int u = 0; u < 2; u++) {
            int f = tid + u * 256;
            int row = f >> 2, seg = (f & 3) * 4;
            unsigned da = (unsigned)__cvta_generic_to_shared(&As[s][row][seg]);
            CPA16(da, A + (size_t)(m0 + row) * K + k0 + seg);
        }
#pragma unroll
        for (int u = 0; u < 2; u++) {
            int f = tid + u * 256;
            int row = f >> 5, off = (f & 31) * 4;
            unsigned db = (unsigned)__cvta_generic_to_shared(&Bs[s][row][off]);
            CPA16(db, W + (size_t)(k0 + row) * N + n0 + off);
        }
        cp_commit();
    }

    for (int kt = 0; kt < KT; kt++) {
        int cur = kt & (GEMM_STAGES - 1);
        asm volatile("cp.async.wait_group %0;" :: "n"(GEMM_STAGES - 2));
        __syncthreads();

        if (kt + GEMM_STAGES - 1 < KT) {
            int s = (kt + GEMM_STAGES - 1) & (GEMM_STAGES - 1);
            int k0 = (kt + GEMM_STAGES - 1) * 16;
#pragma unroll
            for (int u = 0; u < 2; u++) {
                int f = tid + u * 256;
                int row = f >> 2, seg = (f & 3) * 4;
                unsigned da = (unsigned)__cvta_generic_to_shared(&As[s][row][seg]);
                CPA16(da, A + (size_t)(m0 + row) * K + k0 + seg);
            }
#pragma unroll
            for (int u = 0; u < 2; u++) {
                int f = tid + u * 256;
                int row = f >> 5, off = (f & 31) * 4;
                unsigned db = (unsigned)__cvta_generic_to_shared(&Bs[s][row][off]);
                CPA16(db, W + (size_t)(k0 + row) * N + n0 + off);
            }
        }
        cp_commit();

#pragma unroll
        for (int ks = 0; ks < 2; ks++) {
            int kk = ks * 8;
            unsigned af[4][4], bf[4][2];
#pragma unroll
            for (int mt = 0; mt < 4; mt++) {
                int mr = wm + mt * 16 + r;
                af[mt][0] = __float_as_uint(As[cur][mr    ][kk + cq]);
                af[mt][1] = __float_as_uint(As[cur][mr + 8][kk + cq]);
                af[mt][2] = __float_as_uint(As[cur][mr    ][kk + cq + 4]);
                af[mt][3] = __float_as_uint(As[cur][mr + 8][kk + cq + 4]);
            }
#pragma unroll
            for (int nt = 0; nt < 4; nt++) {
                int nn = wn + nt * 8 + r;
                bf[nt][0] = f2tf(Bs[cur][kk + cq    ][nn]);
                bf[nt][1] = f2tf(Bs[cur][kk + cq + 4][nn]);
            }
#pragma unroll
            for (int mt = 0; mt < 4; mt++)
#pragma unroll
                for (int nt = 0; nt < 4; nt++)
                    mma8(acc[mt][nt], af[mt][0], af[mt][1], af[mt][2], af[mt][3],
                         bf[nt][0], bf[nt][1]);
        }
    }

#pragma unroll
    for (int mt = 0; mt < 4; mt++) {
        int row = m0 + wm + mt * 16 + r;
#pragma unroll
        for (int nt = 0; nt < 4; nt++) {
            int col = n0 + wn + nt * 8 + cq * 2;
            float2 bb = *(const float2*)&bias[col];
            float v0 = acc[mt][nt][0] + bb.x;
            float v1 = acc[mt][nt][1] + bb.y;
            float v2 = acc[mt][nt][2] + bb.x;
            float v3 = acc[mt][nt][3] + bb.y;
            if (act) {
                v0 = 0.5f * v0 * (1.0f + erff(v0 * 0.70710678118654752f));
                v1 = 0.5f * v1 * (1.0f + erff(v1 * 0.70710678118654752f));
                v2 = 0.5f * v2 * (1.0f + erff(v2 * 0.70710678118654752f));
                v3 = 0.5f * v3 * (1.0f + erff(v3 * 0.70710678118654752f));
            }
            if (rnd) {
                v0 = roundtf(v0); v1 = roundtf(v1);
                v2 = roundtf(v2); v3 = roundtf(v3);
            }
            *(float2*)&C[(size_t)row * N + col]       = make_float2(v0, v1);
            *(float2*)&C[(size_t)(row + 8) * N + col] = make_float2(v2, v3);
        }
    }
}

// ------- tf32 GEMM split-K: BM=64 BN=128 BK=16, 256 thr, 4-stage --------------
#define G64_STAGES 4
#define G64_SMEM   (G64_STAGES * (64*20 + 16*136) * 4)   // 55296 bytes
__global__ __launch_bounds__(256, 2) void tf32_gemm64_splitk_kernel(
    const float* __restrict__ A, const float* __restrict__ W,
    float* __restrict__ Cpart, int M, int N, int K, int Ks)
{
    extern __shared__ float smem[];
    float (*As)[64][20]  = (float(*)[64][20])smem;
    float (*Bs)[16][136] = (float(*)[16][136])(smem + G64_STAGES*64*20);

    int tid = threadIdx.x;
    int warp = tid >> 5, lane = tid & 31;
    int r = lane >> 2, cq = lane & 3;
    int wm = (warp >> 2) * 32;
    int wn = (warp & 3) * 32;
    int m0 = blockIdx.y * 64, n0 = blockIdx.x * 128;
    int kbase = blockIdx.z * Ks;
    float* C = Cpart + (size_t)blockIdx.z * M * N;

    float acc[2][4][4];
#pragma unroll
    for (int i = 0; i < 2; i++)
#pragma unroll
        for (int j = 0; j < 4; j++)
#pragma unroll
            for (int t = 0; t < 4; t++) acc[i][j][t] = 0.f;

    int KT = Ks / 16;

#pragma unroll
    for (int s = 0; s < G64_STAGES - 1; s++) {
        int k0 = kbase + s * 16;
        {
            int row = tid >> 2, seg = (tid & 3) * 4;
            unsigned da = (unsigned)__cvta_generic_to_shared(&As[s][row][seg]);
            CPA16(da, A + (size_t)(m0 + row) * K + k0 + seg);
        }
#pragma unroll
        for (int u = 0; u < 2; u++) {
            int f = tid + u * 256;
            int row = f >> 5, off = (f & 31) * 4;
            unsigned db = (unsigned)__cvta_generic_to_shared(&Bs[s][row][off]);
            CPA16(db, W + (size_t)(k0 + row) * N + n0 + off);
        }
        cp_commit();
    }

    for (int kt = 0; kt < KT; kt++) {
        int cur = kt & (G64_STAGES - 1);
        asm volatile("cp.async.wait_group %0;" :: "n"(G64_STAGES - 2));
        __syncthreads();

        if (kt + G64_STAGES - 1 < KT) {
            int s = (kt + G64_STAGES - 1) & (G64_STAGES - 1);
            int k0 = kbase + (kt + G64_STAGES - 1) * 16;
            {
                int row = tid >> 2, seg = (tid & 3) * 4;
                unsigned da = (unsigned)__cvta_generic_to_shared(&As[s][row][seg]);
                CPA16(da, A + (size_t)(m0 + row) * K + k0 + seg);
            }
#pragma unroll
            for (int u = 0; u < 2; u++) {
                int f = tid + u * 256;
                int row = f >> 5, off = (f & 31) * 4;
                unsigned db = (unsigned)__cvta_generic_to_shared(&Bs[s][row][off]);
                CPA16(db, W + (size_t)(k0 + row) * N + n0 + off);
            }
        }
        cp_commit();

#pragma unroll
        for (int ks = 0; ks < 2; ks++) {
            int kk = ks * 8;
            unsigned af[2][4], bf[4][2];
#pragma unroll
            for (int mt = 0; mt < 2; mt++) {
                int mr = wm + mt * 16 + r;
                af[mt][0] = __float_as_uint(As[cur][mr    ][kk + cq]);
                af[mt][1] = __float_as_uint(As[cur][mr + 8][kk + cq]);
                af[mt][2] = __float_as_uint(As[cur][mr    ][kk + cq + 4]);
                af[mt][3] = __float_as_uint(As[cur][mr + 8][kk + cq + 4]);
            }
#pragma unroll
            for (int nt = 0; nt < 4; nt++) {
                int nn = wn + nt * 8 + r;
                bf[nt][0] = f2tf(Bs[cur][kk + cq    ][nn]);
                bf[nt][1] = f2tf(Bs[cur][kk + cq + 4][nn]);
            }
#pragma unroll
            for (int mt = 0; mt < 2; mt++)
#pragma unroll
                for (int nt = 0; nt < 4; nt++)
                    mma8(acc[mt][nt], af[mt][0], af[mt][1], af[mt][2], af[mt][3],
                         bf[nt][0], bf[nt][1]);
        }
    }

#pragma unroll
    for (int mt = 0; mt < 2; mt++) {
        int row = m0 + wm + mt * 16 + r;
#pragma unroll
        for (int nt = 0; nt < 4; nt++) {
            int col = n0 + wn + nt * 8 + cq * 2;
            *(float2*)&C[(size_t)row * N + col] =
                make_float2(acc[mt][nt][0], acc[mt][nt][1]);
            *(float2*)&C[(size_t)(row + 8) * N + col] =
                make_float2(acc[mt][nt][2], acc[mt][nt][3]);
        }
    }
}

// ---------------- attention-mask bias -----------------------------------------
__global__ void abias_kernel(const int* __restrict__ mask)
{
    int i = blockIdx.x * blockDim.x + threadIdx.x;
    if (i < BATCH * SEQ) g_abias[i] = (1.f - (float)mask[i]) * -10000.f;
}

// ---------------- flash attention: online softmax, one pass over K/V ----------
// grid (SEQ/64, B*NH), 128 thr (4 warps). Each warp owns 16 full rows.
// smem: QP (Q tile, then reused as P staging) + double-buffered K and V.
// 85 KB -> 2 blocks/SM.
#define ATTN_SMEM ((64*68 * 5) * 4)   // 87040 bytes
__global__ __launch_bounds__(128) void attn_flash_kernel(
    const float* __restrict__ q, const float* __restrict__ k,
    const float* __restrict__ v, float* __restrict__ ctx)
{
    extern __shared__ float sm[];
    float (*QP)[68]     = (float(*)[68])sm;                     // 64x68 (Q, then P)
    float (*Ks)[64][68] = (float(*)[64][68])(sm + 64*68);       // [2][64][68]
    float (*Vs)[64][68] = (float(*)[64][68])(sm + 3*64*68);     // [2][64][68]

    int bh = blockIdx.y;
    int b = bh / NHEADS, h = bh - b * NHEADS;
    int i0 = blockIdx.x * 64;
    int tid = threadIdx.x;
    int warp = tid >> 5, lane = tid & 31;
    int r = lane >> 2, cq = lane & 3;
    int wr = warp * 16;             // warp's 16-row slice

    // load Q tile (64x64): 1024 float4 over 128 threads
#pragma unroll
    for (int u = 0; u < 8; u++) {
        int f = tid + u * 128;
        int row = f >> 4, off = (f & 15) << 2;
        *(float4*)&QP[row][off] =
            *(const float4*)(q + (size_t)(b * SEQ + i0 + row) * Hdim + h * DHEAD + off);
    }
    __syncthreads();

    // Q fragments (warp's 16 rows) into registers
    unsigned aq[8][4];
#pragma unroll
    for (int ks = 0; ks < 8; ks++) {
        int kk = ks * 8;
        int mr = wr + r;
        aq[ks][0] = __float_as_uint(QP[mr    ][kk + cq]);
        aq[ks][1] = __float_as_uint(QP[mr + 8][kk + cq]);
        aq[ks][2] = __float_as_uint(QP[mr    ][kk + cq + 4]);
        aq[ks][3] = __float_as_uint(QP[mr + 8][kk + cq + 4]);
    }
    __syncthreads();   // QP now free for P staging

    // prologue: K0 + V0 into buffer 0 (each 1024 float4 over 128 threads)
#pragma unroll
    for (int u = 0; u < 8; u++) {
        int f = tid + u * 128;
        int row = f >> 4, off = (f & 15) << 2;
        unsigned dk = (unsigned)__cvta_generic_to_shared(&Ks[0][row][off]);
        CPA16(dk, k + (size_t)(b * SEQ + row) * Hdim + h * DHEAD + off);
        unsigned dv = (unsigned)__cvta_generic_to_shared(&Vs[0][row][off]);
        CPA16(dv, v + (size_t)(b * SEQ + row) * Hdim + h * DHEAD + off);
    }
    cp_commit();

    // online-softmax state (thread owns rows wr+r and wr+r+8)
    float m0 = -1e30f, m1 = -1e30f, l0 = 0.f, l1 = 0.f;
    float occ[8][4];
#pragma unroll
    for (int nt = 0; nt < 8; nt++)
#pragma unroll
        for (int t = 0; t < 4; t++) occ[nt][t] = 0.f;

    for (int jt = 0; jt < 8; jt++) {
        int cur = jt & 1;
        __syncthreads();   // all warps done with buffer cur^1
        if (jt + 1 < 8) {
            int j0n = (jt + 1) * 64;
#pragma unroll
            for (int u = 0; u < 8; u++) {
                int f = tid + u * 128;
                int row = f >> 4, off = (f & 15) << 2;
                unsigned dk = (unsigned)__cvta_generic_to_shared(&Ks[cur ^ 1][row][off]);
                CPA16(dk, k + (size_t)(b * SEQ + j0n + row) * Hdim + h * DHEAD + off);
                unsigned dv = (unsigned)__cvta_generic_to_shared(&Vs[cur ^ 1][row][off]);
                CPA16(dv, v + (size_t)(b * SEQ + j0n + row) * Hdim + h * DHEAD + off);
            }
        }
        cp_commit();
        asm volatile("cp.async.wait_group 1;");
        __syncthreads();

        // ---- scores: S(16x64) = Q_warp @ K_j^T ----
        float acc[8][4];
#pragma unroll
        for (int nt = 0; nt < 8; nt++)
#pragma unroll
            for (int t = 0; t < 4; t++) acc[nt][t] = 0.f;

#pragma unroll
        for (int ks = 0; ks < 8; ks++) {
            int kk = ks * 8;
#pragma unroll
            for (int nt = 0; nt < 8; nt++) {
                int nn = nt * 8 + r;
                unsigned b0 = __float_as_uint(Ks[cur][nn][kk + cq]);
                unsigned b1 = __float_as_uint(Ks[cur][nn][kk + cq + 4]);
                mma8(acc[nt], aq[ks][0], aq[ks][1], aq[ks][2], aq[ks][3], b0, b1);
            }
        }

        // ---- scale + bias, tile row max ----
        int j0 = jt * 64;
        float tmax0 = -1e30f, tmax1 = -1e30f;
#pragma unroll
        for (int nt = 0; nt < 8; nt++) {
            int jc = j0 + nt * 8 + cq * 2;
            float2 ab = *(const float2*)&g_abias[b * SEQ + jc];
            acc[nt][0] = acc[nt][0] * 0.125f + ab.x;
            acc[nt][1] = acc[nt][1] * 0.125f + ab.y;
            acc[nt][2] = acc[nt][2] * 0.125f + ab.x;
            acc[nt][3] = acc[nt][3] * 0.125f + ab.y;
            tmax0 = fmaxf(tmax0, fmaxf(acc[nt][0], acc[nt][1]));
            tmax1 = fmaxf(tmax1, fmaxf(acc[nt][2], acc[nt][3]));
        }
        // reduce over the 4 lanes sharing a row (cq group: lane = 4r + cq)
        tmax0 = fmaxf(tmax0, __shfl_xor_sync(0xFFFFFFFFu, tmax0, 1));
        tmax0 = fmaxf(tmax0, __shfl_xor_sync(0xFFFFFFFFu, tmax0, 2));
        tmax1 = fmaxf(tmax1, __shfl_xor_sync(0xFFFFFFFFu, tmax1, 1));
        tmax1 = fmaxf(tmax1, __shfl_xor_sync(0xFFFFFFFFu, tmax1, 2));

        float mn0 = fmaxf(m0, tmax0), mn1 = fmaxf(m1, tmax1);
        float f0 = expf(m0 - mn0), f1 = expf(m1 - mn1);
        float s0 = 0.f, s1 = 0.f;

        // ---- exp + write P to smem (tf32-rounded) ----
#pragma unroll
        for (int nt = 0; nt < 8; nt++) {
            float p0 = expf(acc[nt][0] - mn0);
            float p1 = expf(acc[nt][1] - mn0);
            float p2 = expf(acc[nt][2] - mn1);
            float p3 = expf(acc[nt][3] - mn1);
            s0 += p0 + p1;
            s1 += p2 + p3;
            int pc = nt * 8 + cq * 2;
            *(float2*)&QP[wr + r    ][pc] = make_float2(roundtf(p0), roundtf(p1));
            *(float2*)&QP[wr + r + 8][pc] = make_float2(roundtf(p2), roundtf(p3));
        }
        s0 += __shfl_xor_sync(0xFFFFFFFFu, s0, 1);
        s0 += __shfl_xor_sync(0xFFFFFFFFu, s0, 2);
        s1 += __shfl_xor_sync(0xFFFFFFFFu, s1, 1);
        s1 += __shfl_xor_sync(0xFFFFFFFFu, s1, 2);

        l0 = l0 * f0 + s0;
        l1 = l1 * f1 + s1;
        m0 = mn0;
        m1 = mn1;

        // rescale O accumulators
#pragma unroll
        for (int nt = 0; nt < 8; nt++) {
            occ[nt][0] *= f0; occ[nt][1] *= f0;
            occ[nt][2] *= f1; occ[nt][3] *= f1;
        }
        __syncwarp();   // P (own warp's rows) visible within warp

        // ---- P@V: O(16x64) += P(16x64) @ V_j(64x64) ----
#pragma unroll
        for (int kg = 0; kg < 8; kg++) {
            int kk = kg * 8;
            unsigned a0 = __float_as_uint(QP[wr + r    ][kk + cq]);
            unsigned a1 = __float_as_uint(QP[wr + r + 8][kk + cq]);
            unsigned a2 = __float_as_uint(QP[wr + r    ][kk + cq + 4]);
            unsigned a3 = __float_as_uint(QP[wr + r + 8][kk + cq + 4]);
#pragma unroll
            for (int nt = 0; nt < 8; nt++) {
                int nn = nt * 8 + r;
                unsigned b0 = __float_as_uint(Vs[cur][kk + cq    ][nn]);
                unsigned b1 = __float_as_uint(Vs[cur][kk + cq + 4][nn]);
                mma8(occ[nt], a0, a1, a2, a3, b0, b1);
            }
        }
        __syncwarp();   // done reading P before next jt overwrites
    }

    // ---- normalize + write ctx (tf32-rounded, feeds O-proj) ----
    float inv0 = 1.f / l0, inv1 = 1.f / l1;
    int irow = b * SEQ + i0 + wr + r;
#pragma unroll
    for (int nt = 0; nt < 8; nt++) {
        int col = h * DHEAD + nt * 8 + cq * 2;
        *(float2*)&ctx[(size_t)irow * Hdim + col] =
            make_float2(roundtf(occ[nt][0] * inv0), roundtf(occ[nt][1] * inv0));
        *(float2*)&ctx[(size_t)(irow + 8) * Hdim + col] =
            make_float2(roundtf(occ[nt][2] * inv1), roundtf(occ[nt][3] * inv1));
    }
}

// ---------------- heads: entity logits + pi/pj for relations ------------------
__global__ __launch_bounds__(256) void heads_kernel(
    const float* __restrict__ x, const float* __restrict__ W_ent,
    const float* __restrict__ b_ent, const float* __restrict__ W_rel,
    const float* __restrict__ b_rel, float* __restrict__ ent_out)
{
    int t = blockIdx.x;
    int tid = threadIdx.x;
    __shared__ float xs[Hdim];
    for (int i = tid; i < Hdim; i += 256) xs[i] = x[(size_t)t * Hdim + i];
    __syncthreads();
    int warp = tid >> 5, lane = tid & 31;
    for (int o = warp; o < NEnt + 2 * NRel; o += 8) {
        float s = 0.f;
        if (o < NEnt) {
            for (int k = lane; k < Hdim; k += 32) s += xs[k] * W_ent[(size_t)k * NEnt + o];
        } else if (o < NEnt + NRel) {
            int rr = o - NEnt;
            for (int k = lane; k < Hdim; k += 32) s += xs[k] * W_rel[(size_t)k * NRel + rr];
        } else {
            int rr = o - NEnt - NRel;
            for (int k = lane; k < Hdim; k += 32) s += xs[k] * W_rel[(size_t)(Hdim + k) * NRel + rr];
        }
#pragma unroll
        for (int off = 16; off; off >>= 1) s += __shfl_xor_sync(0xFFFFFFFFu, s, off);
        if (lane == 0) {
            if (o < NEnt)             ent_out[(size_t)t * NEnt + o] = s + b_ent[o];
            else if (o < NEnt + NRel) g_pi[t * NRel + (o - NEnt)] = s;
            else                      g_pj[t * NRel + (o - NEnt - NRel)] = s + b_rel[o - NEnt - NRel];
        }
    }
}

// ---------------- relation broadcast ------------------------------------------
__global__ __launch_bounds__(256) void relation_kernel(float* __restrict__ out)
{
    int bi = blockIdx.x;
    int b = bi >> 9;
    __shared__ float ps[NRel];
    if (threadIdx.x < NRel) ps[threadIdx.x] = g_pi[bi * NRel + threadIdx.x];
    __syncthreads();
    const float* pjb = g_pj + (size_t)(b << 9) * NRel;
    float* o = out + (size_t)bi * SEQ * NRel;
    for (int idx = threadIdx.x; idx < SEQ * NRel; idx += 256) {
        int r = idx % NRel;
        o[idx] = ps[r] + pjb[idx];
    }
}

// ---------------- host orchestration -----------------------------------------
extern "C" void kernel_launch(void* const* d_in, const int* in_sizes, int n_in,
                              void* d_out, int out_size)
{
    const int*   input_ids = (const int*)  d_in[0];
    const int*   attn_mask = (const int*)  d_in[1];
    const float* emb_word  = (const float*)d_in[2];
    const float* emb_pos   = (const float*)d_in[3];
    const float* emb_type  = (const float*)d_in[4];
    const float* emb_ln_g  = (const float*)d_in[5];
    const float* emb_ln_b  = (const float*)d_in[6];
    const float* Wq = (const float*)d_in[7];
    const float* bq = (const float*)d_in[8];
    const float* Wk = (const float*)d_in[9];
    const float* bk = (const float*)d_in[10];
    const float* Wv = (const float*)d_in[11];
    const float* bv = (const float*)d_in[12];
    const float* Wo = (const float*)d_in[13];
    const float* bo = (const float*)d_in[14];
    const float* ln1_g = (const float*)d_in[15];
    const float* ln1_b = (const float*)d_in[16];
    const float* W1 = (const float*)d_in[17];
    const float* b1 = (const float*)d_in[18];
    const float* W2 = (const float*)d_in[19];
    const float* b2 = (const float*)d_in[20];
    const float* ln2_g = (const float*)d_in[21];
    const float* ln2_b = (const float*)d_in[22];
    const float* W_ent = (const float*)d_in[23];
    const float* b_ent = (const float*)d_in[24];
    const float* W_rel = (const float*)d_in[25];
    const float* b_rel = (const float*)d_in[26];

    float *x, *xr, *q, *k, *v, *ctx, *ffn, *part;
    cudaGetSymbolAddress((void**)&x,    g_x);
    cudaGetSymbolAddress((void**)&xr,   g_xr);
    cudaGetSymbolAddress((void**)&q,    g_q);
    cudaGetSymbolAddress((void**)&k,    g_k);
    cudaGetSymbolAddress((void**)&v,    g_v);
    cudaGetSymbolAddress((void**)&ctx,  g_ctx);
    cudaGetSymbolAddress((void**)&ffn,  g_ffn);
    cudaGetSymbolAddress((void**)&part, g_part);

    cudaFuncSetAttribute(attn_flash_kernel,
                         cudaFuncAttributeMaxDynamicSharedMemorySize, ATTN_SMEM);
    cudaFuncSetAttribute(tf32_gemm_kernel,
                         cudaFuncAttributeMaxDynamicSharedMemorySize, GEMM_SMEM);
    cudaFuncSetAttribute(tf32_gemm64_splitk_kernel,
                         cudaFuncAttributeMaxDynamicSharedMemorySize, G64_SMEM);

    embed_ln_kernel<<<MTOK, 256>>>(input_ids, emb_word, emb_pos, emb_type,
                                   emb_ln_g, emb_ln_b);
    abias_kernel<<<(BATCH * SEQ + 255) / 256, 256>>>(attn_mask);

    dim3 gQKV(Hdim / 128, MTOK / 128, 3);
    dim3 gF1(FFdim / 128, MTOK / 128, 1);
    dim3 gSK(Hdim / 128, MTOK / 64, NSPLIT);  // 6 x 32 x 3 = 576 blocks
    dim3 gA(SEQ / 64, BATCH * NHEADS);        // 8 x 48 = 384 blocks

    for (int l = 0; l < NLAY; l++) {
        size_t wHH = (size_t)l * Hdim * Hdim;
        size_t wH  = (size_t)l * Hdim;
        size_t wHF = (size_t)l * Hdim * FFdim;
        tf32_gemm_kernel<<<gQKV, 256, GEMM_SMEM>>>(xr, Wq + wHH, Wk + wHH, Wv + wHH,
                                        bq + wH, bk + wH, bv + wH,
                                        q, k, v, MTOK, Hdim, Hdim, 0, 1);
        attn_flash_kernel<<<gA, 128, ATTN_SMEM>>>(q, k, v, ctx);
        tf32_gemm64_splitk_kernel<<<gSK, 256, G64_SMEM>>>(ctx, Wo + wHH, part,
                                                          MTOK, Hdim, Hdim, Hdim / NSPLIT);
        reduce3_add_ln_kernel<<<MTOK, 256>>>(part, bo + wH, x, ln1_g + wH, ln1_b + wH);
        tf32_gemm_kernel<<<gF1, 256, GEMM_SMEM>>>(xr, W1 + wHF, W1 + wHF, W1 + wHF,
                                       b1 + (size_t)l * FFdim, b1 + (size_t)l * FFdim, b1 + (size_t)l * FFdim,
                                       ffn, ffn, ffn, MTOK, FFdim, Hdim, 1, 1);
        tf32_gemm64_splitk_kernel<<<gSK, 256, G64_SMEM>>>(ffn, W2 + wHF, part,
                                                          MTOK, Hdim, FFdim, FFdim / NSPLIT);
        reduce3_add_ln_kernel<<<MTOK, 256>>>(part, b2 + wH, x, ln2_g + wH, ln2_b + wH);
    }

    float* out = (float*)d_out;
    heads_kernel<<<MTOK, 256>>>(x, W_ent, b_ent, W_rel, b_rel, out);
    relation_kernel<<<MTOK, 256>>>(out + (size_t)MTOK * NEnt);
}

// round 13
// speedup vs baseline: 1.2327x; 1.0312x over previous
#include <cuda_runtime.h>
#include <math.h>

#define Hdim   768
#define FFdim  3072
#define NLAY   12
#define NHEADS 12
#define DHEAD  64
#define BATCH  4
#define SEQ    512
#define MTOK   (BATCH*SEQ)   // 2048
#define NEnt   12
#define NRel   13
#define NSPLIT 3

// ---------------- scratch (static device globals; no allocation) -------------
__device__ float g_x[MTOK*Hdim];
__device__ float g_xr[MTOK*Hdim];      // tf32-rounded copy of x (GEMM A side)
__device__ float g_q[MTOK*Hdim];
__device__ float g_k[MTOK*Hdim];
__device__ float g_v[MTOK*Hdim];
__device__ float g_ctx[MTOK*Hdim];
__device__ float g_ffn[MTOK*FFdim];
__device__ float g_part[(size_t)NSPLIT*MTOK*Hdim];   // split-K partials
__device__ float g_pi[MTOK*NRel];
__device__ float g_pj[MTOK*NRel];
__device__ float g_abias[BATCH*SEQ];

// ---------------- tf32 helpers ------------------------------------------------
__device__ __forceinline__ unsigned f2tf(float f) {
    unsigned u;
    asm("cvt.rna.tf32.f32 %0, %1;" : "=r"(u) : "f"(f));
    return u;
}
__device__ __forceinline__ float roundtf(float f) { return __uint_as_float(f2tf(f)); }
__device__ __forceinline__ void mma8(float* c, unsigned a0, unsigned a1,
                                     unsigned a2, unsigned a3,
                                     unsigned b0, unsigned b1) {
    asm volatile(
        "mma.sync.aligned.m16n8k8.row.col.f32.tf32.tf32.f32 "
        "{%0,%1,%2,%3},{%4,%5,%6,%7},{%8,%9},{%0,%1,%2,%3};"
        : "+f"(c[0]), "+f"(c[1]), "+f"(c[2]), "+f"(c[3])
        : "r"(a0), "r"(a1), "r"(a2), "r"(a3), "r"(b0), "r"(b1));
}
#define CPA16(dst, src) \
    asm volatile("cp.async.ca.shared.global [%0], [%1], 16;" :: "r"(dst), "l"(src))
__device__ __forceinline__ void cp_commit() { asm volatile("cp.async.commit_group;"); }

// ---------------- embedding + LayerNorm ---------------------------------------
__global__ __launch_bounds__(256) void embed_ln_kernel(
    const int* __restrict__ ids, const float* __restrict__ ew,
    const float* __restrict__ ep, const float* __restrict__ et,
    const float* __restrict__ g, const float* __restrict__ b)
{
    int t = blockIdx.x;
    int s = t & (SEQ - 1);
    int id = ids[t];
    int tid = threadIdx.x;
    float vals[3];
    float sum = 0.f;
#pragma unroll
    for (int i = 0; i < 3; i++) {
        int c = tid + i * 256;
        vals[i] = ew[(size_t)id * Hdim + c] + ep[(size_t)s * Hdim + c] + et[c];
        sum += vals[i];
    }
    __shared__ float red[256];
    red[tid] = sum; __syncthreads();
    for (int o = 128; o; o >>= 1) { if (tid < o) red[tid] += red[tid + o]; __syncthreads(); }
    float mean = red[0] * (1.f / Hdim);
    __syncthreads();
    float sq = 0.f;
#pragma unroll
    for (int i = 0; i < 3; i++) { float d = vals[i] - mean; sq += d * d; }
    red[tid] = sq; __syncthreads();
    for (int o = 128; o; o >>= 1) { if (tid < o) red[tid] += red[tid + o]; __syncthreads(); }
    float rstd = rsqrtf(red[0] * (1.f / Hdim) + 1e-12f);
#pragma unroll
    for (int i = 0; i < 3; i++) {
        int c = tid + i * 256;
        float v = (vals[i] - mean) * rstd * g[c] + b[c];
        g_x [(size_t)t * Hdim + c] = v;
        g_xr[(size_t)t * Hdim + c] = roundtf(v);
    }
}

// ------- split-K reduction + bias + residual add + LayerNorm (in-place x) -----
__global__ __launch_bounds__(256) void reduce3_add_ln_kernel(
    const float* __restrict__ part, const float* __restrict__ bias,
    float* __restrict__ x,
    const float* __restrict__ g, const float* __restrict__ b)
{
    const size_t MN = (size_t)MTOK * Hdim;
    int t = blockIdx.x;
    int tid = threadIdx.x;
    float vals[3];
    float sum = 0.f;
#pragma unroll
    for (int i = 0; i < 3; i++) {
        int c = tid + i * 256;
        size_t idx = (size_t)t * Hdim + c;
        float y = part[idx] + part[MN + idx] + part[2 * MN + idx] + bias[c];
        vals[i] = x[idx] + y;
        sum += vals[i];
    }
    __shared__ float red[256];
    red[tid] = sum; __syncthreads();
    for (int o = 128; o; o >>= 1) { if (tid < o) red[tid] += red[tid + o]; __syncthreads(); }
    float mean = red[0] * (1.f / Hdim);
    __syncthreads();
    float sq = 0.f;
#pragma unroll
    for (int i = 0; i < 3; i++) { float d = vals[i] - mean; sq += d * d; }
    red[tid] = sq; __syncthreads();
    for (int o = 128; o; o >>= 1) { if (tid < o) red[tid] += red[tid + o]; __syncthreads(); }
    float rstd = rsqrtf(red[0] * (1.f / Hdim) + 1e-12f);
#pragma unroll
    for (int i = 0; i < 3; i++) {
        int c = tid + i * 256;
        float v = (vals[i] - mean) * rstd * g[c] + b[c];
        x[(size_t)t * Hdim + c] = v;
        g_xr[(size_t)t * Hdim + c] = roundtf(v);
    }
}

// ---------------- tf32 GEMM: BM=128 BN=128 BK=16, 256 thr, 4-stage ------------
#define GEMM_STAGES 4
#define GEMM_SMEM   (GEMM_STAGES * (128*20 + 16*136) * 4)   // 75776 bytes
__global__ __launch_bounds__(256, 2) void tf32_gemm_kernel(
    const float* __restrict__ A,
    const float* __restrict__ W0, const float* __restrict__ W1, const float* __restrict__ W2,
    const float* __restrict__ bias0, const float* __restrict__ bias1, const float* __restrict__ bias2,
    float* __restrict__ C0, float* __restrict__ C1, float* __restrict__ C2,
    int M, int N, int K, int act, int rnd)
{
    int z = blockIdx.z;
    const float* W    = (z == 0) ? W0    : (z == 1) ? W1    : W2;
    const float* bias = (z == 0) ? bias0 : (z == 1) ? bias1 : bias2;
    float*       C    = (z == 0) ? C0    : (z == 1) ? C1    : C2;

    extern __shared__ float smem[];
    float (*As)[128][20]  = (float(*)[128][20])smem;
    float (*Bs)[16][136]  = (float(*)[16][136])(smem + GEMM_STAGES*128*20);

    int tid = threadIdx.x;
    int warp = tid >> 5, lane = tid & 31;
    int r = lane >> 2, cq = lane & 3;
    int wm = (warp >> 2) * 64;
    int wn = (warp & 3) * 32;
    int m0 = blockIdx.y * 128, n0 = blockIdx.x * 128;

    float acc[4][4][4];
#pragma unroll
    for (int i = 0; i < 4; i++)
#pragma unroll
        for (int j = 0; j < 4; j++)
#pragma unroll
            for (int t = 0; t < 4; t++) acc[i][j][t] = 0.f;

    int KT = K / 16;

#pragma unroll
    for (int s = 0; s < GEMM_STAGES - 1; s++) {
        int k0 = s * 16;
#pragma unroll
        for (int u = 0; u < 2; u++) {
            int f = tid + u * 256;
            int row = f >> 2, seg = (f & 3) * 4;
            unsigned da = (unsigned)__cvta_generic_to_shared(&As[s][row][seg]);
            CPA16(da, A + (size_t)(m0 + row) * K + k0 + seg);
        }
#pragma unroll
        for (int u = 0; u < 2; u++) {
            int f = tid + u * 256;
            int row = f >> 5, off = (f & 31) * 4;
            unsigned db = (unsigned)__cvta_generic_to_shared(&Bs[s][row][off]);
            CPA16(db, W + (size_t)(k0 + row) * N + n0 + off);
        }
        cp_commit();
    }

    for (int kt = 0; kt < KT; kt++) {
        int cur = kt & (GEMM_STAGES - 1);
        asm volatile("cp.async.wait_group %0;" :: "n"(GEMM_STAGES - 2));
        __syncthreads();

        if (kt + GEMM_STAGES - 1 < KT) {
            int s = (kt + GEMM_STAGES - 1) & (GEMM_STAGES - 1);
            int k0 = (kt + GEMM_STAGES - 1) * 16;
#pragma unroll
            for (int u = 0; u < 2; u++) {
                int f = tid + u * 256;
                int row = f >> 2, seg = (f & 3) * 4;
                unsigned da = (unsigned)__cvta_generic_to_shared(&As[s][row][seg]);
                CPA16(da, A + (size_t)(m0 + row) * K + k0 + seg);
            }
#pragma unroll
            for (int u = 0; u < 2; u++) {
                int f = tid + u * 256;
                int row = f >> 5, off = (f & 31) * 4;
                unsigned db = (unsigned)__cvta_generic_to_shared(&Bs[s][row][off]);
                CPA16(db, W + (size_t)(k0 + row) * N + n0 + off);
            }
        }
        cp_commit();

#pragma unroll
        for (int ks = 0; ks < 2; ks++) {
            int kk = ks * 8;
            unsigned af[4][4], bf[4][2];
#pragma unroll
            for (int mt = 0; mt < 4; mt++) {
                int mr = wm + mt * 16 + r;
                af[mt][0] = __float_as_uint(As[cur][mr    ][kk + cq]);
                af[mt][1] = __float_as_uint(As[cur][mr + 8][kk + cq]);
                af[mt][2] = __float_as_uint(As[cur][mr    ][kk + cq + 4]);
                af[mt][3] = __float_as_uint(As[cur][mr + 8][kk + cq + 4]);
            }
#pragma unroll
            for (int nt = 0; nt < 4; nt++) {
                int nn = wn + nt * 8 + r;
                bf[nt][0] = f2tf(Bs[cur][kk + cq    ][nn]);
                bf[nt][1] = f2tf(Bs[cur][kk + cq + 4][nn]);
            }
#pragma unroll
            for (int mt = 0; mt < 4; mt++)
#pragma unroll
                for (int nt = 0; nt < 4; nt++)
                    mma8(acc[mt][nt], af[mt][0], af[mt][1], af[mt][2], af[mt][3],
                         bf[nt][0], bf[nt][1]);
        }
    }

#pragma unroll
    for (int mt = 0; mt < 4; mt++) {
        int row = m0 + wm + mt * 16 + r;
#pragma unroll
        for (int nt = 0; nt < 4; nt++) {
            int col = n0 + wn + nt * 8 + cq * 2;
            float2 bb = *(const float2*)&bias[col];
            float v0 = acc[mt][nt][0] + bb.x;
            float v1 = acc[mt][nt][1] + bb.y;
            float v2 = acc[mt][nt][2] + bb.x;
            float v3 = acc[mt][nt][3] + bb.y;
            if (act) {
                v0 = 0.5f * v0 * (1.0f + erff(v0 * 0.70710678118654752f));
                v1 = 0.5f * v1 * (1.0f + erff(v1 * 0.70710678118654752f));
                v2 = 0.5f * v2 * (1.0f + erff(v2 * 0.70710678118654752f));
                v3 = 0.5f * v3 * (1.0f + erff(v3 * 0.70710678118654752f));
            }
            if (rnd) {
                v0 = roundtf(v0); v1 = roundtf(v1);
                v2 = roundtf(v2); v3 = roundtf(v3);
            }
            *(float2*)&C[(size_t)row * N + col]       = make_float2(v0, v1);
            *(float2*)&C[(size_t)(row + 8) * N + col] = make_float2(v2, v3);
        }
    }
}

// ------- tf32 GEMM split-K: BM=64 BN=128 BK=16, 256 thr, 4-stage --------------
#define G64_STAGES 4
#define G64_SMEM   (G64_STAGES * (64*20 + 16*136) * 4)   // 55296 bytes
__global__ __launch_bounds__(256, 2) void tf32_gemm64_splitk_kernel(
    const float* __restrict__ A, const float* __restrict__ W,
    float* __restrict__ Cpart, int M, int N, int K, int Ks)
{
    extern __shared__ float smem[];
    float (*As)[64][20]  = (float(*)[64][20])smem;
    float (*Bs)[16][136] = (float(*)[16][136])(smem + G64_STAGES*64*20);

    int tid = threadIdx.x;
    int warp = tid >> 5, lane = tid & 31;
    int r = lane >> 2, cq = lane & 3;
    int wm = (warp >> 2) * 32;
    int wn = (warp & 3) * 32;
    int m0 = blockIdx.y * 64, n0 = blockIdx.x * 128;
    int kbase = blockIdx.z * Ks;
    float* C = Cpart + (size_t)blockIdx.z * M * N;

    float acc[2][4][4];
#pragma unroll
    for (int i = 0; i < 2; i++)
#pragma unroll
        for (int j = 0; j < 4; j++)
#pragma unroll
            for (int t = 0; t < 4; t++) acc[i][j][t] = 0.f;

    int KT = Ks / 16;

#pragma unroll
    for (int s = 0; s < G64_STAGES - 1; s++) {
        int k0 = kbase + s * 16;
        {
            int row = tid >> 2, seg = (tid & 3) * 4;
            unsigned da = (unsigned)__cvta_generic_to_shared(&As[s][row][seg]);
            CPA16(da, A + (size_t)(m0 + row) * K + k0 + seg);
        }
#pragma unroll
        for (int u = 0; u < 2; u++) {
            int f = tid + u * 256;
            int row = f >> 5, off = (f & 31) * 4;
            unsigned db = (unsigned)__cvta_generic_to_shared(&Bs[s][row][off]);
            CPA16(db, W + (size_t)(k0 + row) * N + n0 + off);
        }
        cp_commit();
    }

    for (int kt = 0; kt < KT; kt++) {
        int cur = kt & (G64_STAGES - 1);
        asm volatile("cp.async.wait_group %0;" :: "n"(G64_STAGES - 2));
        __syncthreads();

        if (kt + G64_STAGES - 1 < KT) {
            int s = (kt + G64_STAGES - 1) & (G64_STAGES - 1);
            int k0 = kbase + (kt + G64_STAGES - 1) * 16;
            {
                int row = tid >> 2, seg = (tid & 3) * 4;
                unsigned da = (unsigned)__cvta_generic_to_shared(&As[s][row][seg]);
                CPA16(da, A + (size_t)(m0 + row) * K + k0 + seg);
            }
#pragma unroll
            for (int u = 0; u < 2; u++) {
                int f = tid + u * 256;
                int row = f >> 5, off = (f & 31) * 4;
                unsigned db = (unsigned)__cvta_generic_to_shared(&Bs[s][row][off]);
                CPA16(db, W + (size_t)(k0 + row) * N + n0 + off);
            }
        }
        cp_commit();

#pragma unroll
        for (int ks = 0; ks < 2; ks++) {
            int kk = ks * 8;
            unsigned af[2][4], bf[4][2];
#pragma unroll
            for (int mt = 0; mt < 2; mt++) {
                int mr = wm + mt * 16 + r;
                af[mt][0] = __float_as_uint(As[cur][mr    ][kk + cq]);
                af[mt][1] = __float_as_uint(As[cur][mr + 8][kk + cq]);
                af[mt][2] = __float_as_uint(As[cur][mr    ][kk + cq + 4]);
                af[mt][3] = __float_as_uint(As[cur][mr + 8][kk + cq + 4]);
            }
#pragma unroll
            for (int nt = 0; nt < 4; nt++) {
                int nn = wn + nt * 8 + r;
                bf[nt][0] = f2tf(Bs[cur][kk + cq    ][nn]);
                bf[nt][1] = f2tf(Bs[cur][kk + cq + 4][nn]);
            }
#pragma unroll
            for (int mt = 0; mt < 2; mt++)
#pragma unroll
                for (int nt = 0; nt < 4; nt++)
                    mma8(acc[mt][nt], af[mt][0], af[mt][1], af[mt][2], af[mt][3],
                         bf[nt][0], bf[nt][1]);
        }
    }

#pragma unroll
    for (int mt = 0; mt < 2; mt++) {
        int row = m0 + wm + mt * 16 + r;
#pragma unroll
        for (int nt = 0; nt < 4; nt++) {
            int col = n0 + wn + nt * 8 + cq * 2;
            *(float2*)&C[(size_t)row * N + col] =
                make_float2(acc[mt][nt][0], acc[mt][nt][1]);
            *(float2*)&C[(size_t)(row + 8) * N + col] =
                make_float2(acc[mt][nt][2], acc[mt][nt][3]);
        }
    }
}

// ---------------- attention-mask bias -----------------------------------------
__global__ void abias_kernel(const int* __restrict__ mask)
{
    int i = blockIdx.x * blockDim.x + threadIdx.x;
    if (i < BATCH * SEQ) g_abias[i] = (1.f - (float)mask[i]) * -10000.f;
}

// ---------------- flash attention: online softmax, 32-row K/V chunks ----------
// grid (SEQ/64, B*NH), 128 thr (4 warps), each warp owns 16 rows.
// smem 51 KB -> 4 blocks/SM; all 384 blocks co-resident in one wave.
#define ATTN_SMEM ((64*68 + 4*32*68) * 4)   // 52224 bytes
__global__ __launch_bounds__(128, 4) void attn_flash_kernel(
    const float* __restrict__ q, const float* __restrict__ k,
    const float* __restrict__ v, float* __restrict__ ctx)
{
    extern __shared__ float sm[];
    float (*QP)[68]     = (float(*)[68])sm;                     // 64x68 (Q, then P)
    float (*Ks)[32][68] = (float(*)[32][68])(sm + 64*68);       // [2][32][68]
    float (*Vs)[32][68] = (float(*)[32][68])(sm + 64*68 + 2*32*68); // [2][32][68]

    int bh = blockIdx.y;
    int b = bh / NHEADS, h = bh - b * NHEADS;
    int i0 = blockIdx.x * 64;
    int tid = threadIdx.x;
    int warp = tid >> 5, lane = tid & 31;
    int r = lane >> 2, cq = lane & 3;
    int wr = warp * 16;             // warp's 16-row slice

    // load Q tile (64x64): 1024 float4 over 128 threads
#pragma unroll
    for (int u = 0; u < 8; u++) {
        int f = tid + u * 128;
        int row = f >> 4, off = (f & 15) << 2;
        *(float4*)&QP[row][off] =
            *(const float4*)(q + (size_t)(b * SEQ + i0 + row) * Hdim + h * DHEAD + off);
    }
    __syncthreads();

    // Q fragments (warp's 16 rows) into registers
    unsigned aq[8][4];
#pragma unroll
    for (int ks = 0; ks < 8; ks++) {
        int kk = ks * 8;
        int mr = wr + r;
        aq[ks][0] = __float_as_uint(QP[mr    ][kk + cq]);
        aq[ks][1] = __float_as_uint(QP[mr + 8][kk + cq]);
        aq[ks][2] = __float_as_uint(QP[mr    ][kk + cq + 4]);
        aq[ks][3] = __float_as_uint(QP[mr + 8][kk + cq + 4]);
    }
    __syncthreads();   // QP now free for P staging

    // prologue: K0 + V0 chunk (rows 0..31): 512 float4 each over 128 threads
#pragma unroll
    for (int u = 0; u < 4; u++) {
        int f = tid + u * 128;
        int row = f >> 4, off = (f & 15) << 2;
        unsigned dk = (unsigned)__cvta_generic_to_shared(&Ks[0][row][off]);
        CPA16(dk, k + (size_t)(b * SEQ + row) * Hdim + h * DHEAD + off);
        unsigned dv = (unsigned)__cvta_generic_to_shared(&Vs[0][row][off]);
        CPA16(dv, v + (size_t)(b * SEQ + row) * Hdim + h * DHEAD + off);
    }
    cp_commit();

    // online-softmax state (thread owns rows wr+r and wr+r+8)
    float m0 = -1e30f, m1 = -1e30f, l0 = 0.f, l1 = 0.f;
    float occ[8][4];
#pragma unroll
    for (int nt = 0; nt < 8; nt++)
#pragma unroll
        for (int t = 0; t < 4; t++) occ[nt][t] = 0.f;

    for (int jt = 0; jt < 16; jt++) {
        int cur = jt & 1;
        __syncthreads();   // all warps done with buffer cur^1
        if (jt + 1 < 16) {
            int j0n = (jt + 1) * 32;
#pragma unroll
            for (int u = 0; u < 4; u++) {
                int f = tid + u * 128;
                int row = f >> 4, off = (f & 15) << 2;
                unsigned dk = (unsigned)__cvta_generic_to_shared(&Ks[cur ^ 1][row][off]);
                CPA16(dk, k + (size_t)(b * SEQ + j0n + row) * Hdim + h * DHEAD + off);
                unsigned dv = (unsigned)__cvta_generic_to_shared(&Vs[cur ^ 1][row][off]);
                CPA16(dv, v + (size_t)(b * SEQ + j0n + row) * Hdim + h * DHEAD + off);
            }
        }
        cp_commit();
        asm volatile("cp.async.wait_group 1;");
        __syncthreads();

        // ---- scores: S(16x32) = Q_warp @ K_chunk^T ----
        float acc[4][4];
#pragma unroll
        for (int nt = 0; nt < 4; nt++)
#pragma unroll
            for (int t = 0; t < 4; t++) acc[nt][t] = 0.f;

#pragma unroll
        for (int ks = 0; ks < 8; ks++) {
            int kk = ks * 8;
#pragma unroll
            for (int nt = 0; nt < 4; nt++) {
                int nn = nt * 8 + r;
                unsigned b0 = __float_as_uint(Ks[cur][nn][kk + cq]);
                unsigned b1 = __float_as_uint(Ks[cur][nn][kk + cq + 4]);
                mma8(acc[nt], aq[ks][0], aq[ks][1], aq[ks][2], aq[ks][3], b0, b1);
            }
        }

        // ---- scale + bias, chunk row max ----
        int j0 = jt * 32;
        float tmax0 = -1e30f, tmax1 = -1e30f;
#pragma unroll
        for (int nt = 0; nt < 4; nt++) {
            int jc = j0 + nt * 8 + cq * 2;
            float2 ab = *(const float2*)&g_abias[b * SEQ + jc];
            acc[nt][0] = acc[nt][0] * 0.125f + ab.x;
            acc[nt][1] = acc[nt][1] * 0.125f + ab.y;
            acc[nt][2] = acc[nt][2] * 0.125f + ab.x;
            acc[nt][3] = acc[nt][3] * 0.125f + ab.y;
            tmax0 = fmaxf(tmax0, fmaxf(acc[nt][0], acc[nt][1]));
            tmax1 = fmaxf(tmax1, fmaxf(acc[nt][2], acc[nt][3]));
        }
        // reduce over the 4 lanes sharing a row
        tmax0 = fmaxf(tmax0, __shfl_xor_sync(0xFFFFFFFFu, tmax0, 1));
        tmax0 = fmaxf(tmax0, __shfl_xor_sync(0xFFFFFFFFu, tmax0, 2));
        tmax1 = fmaxf(tmax1, __shfl_xor_sync(0xFFFFFFFFu, tmax1, 1));
        tmax1 = fmaxf(tmax1, __shfl_xor_sync(0xFFFFFFFFu, tmax1, 2));

        float mn0 = fmaxf(m0, tmax0), mn1 = fmaxf(m1, tmax1);
        float f0 = expf(m0 - mn0), f1 = expf(m1 - mn1);
        float s0 = 0.f, s1 = 0.f;

        // ---- exp + write P to smem (tf32-rounded) ----
#pragma unroll
        for (int nt = 0; nt < 4; nt++) {
            float p0 = expf(acc[nt][0] - mn0);
            float p1 = expf(acc[nt][1] - mn0);
            float p2 = expf(acc[nt][2] - mn1);
            float p3 = expf(acc[nt][3] - mn1);
            s0 += p0 + p1;
            s1 += p2 + p3;
            int pc = nt * 8 + cq * 2;
            *(float2*)&QP[wr + r    ][pc] = make_float2(roundtf(p0), roundtf(p1));
            *(float2*)&QP[wr + r + 8][pc] = make_float2(roundtf(p2), roundtf(p3));
        }
        s0 += __shfl_xor_sync(0xFFFFFFFFu, s0, 1);
        s0 += __shfl_xor_sync(0xFFFFFFFFu, s0, 2);
        s1 += __shfl_xor_sync(0xFFFFFFFFu, s1, 1);
        s1 += __shfl_xor_sync(0xFFFFFFFFu, s1, 2);

        l0 = l0 * f0 + s0;
        l1 = l1 * f1 + s1;
        m0 = mn0;
        m1 = mn1;

        // rescale O accumulators
#pragma unroll
        for (int nt = 0; nt < 8; nt++) {
            occ[nt][0] *= f0; occ[nt][1] *= f0;
            occ[nt][2] *= f1; occ[nt][3] *= f1;
        }
        __syncwarp();   // P (own warp's rows) visible within warp

        // ---- P@V: O(16x64) += P(16x32) @ V_chunk(32x64) ----
#pragma unroll
        for (int kg = 0; kg < 4; kg++) {
            int kk = kg * 8;
            unsigned a0 = __float_as_uint(QP[wr + r    ][kk + cq]);
            unsigned a1 = __float_as_uint(QP[wr + r + 8][kk + cq]);
            unsigned a2 = __float_as_uint(QP[wr + r    ][kk + cq + 4]);
            unsigned a3 = __float_as_uint(QP[wr + r + 8][kk + cq + 4]);
#pragma unroll
            for (int nt = 0; nt < 8; nt++) {
                int nn = nt * 8 + r;
                unsigned b0 = __float_as_uint(Vs[cur][kk + cq    ][nn]);
                unsigned b1 = __float_as_uint(Vs[cur][kk + cq + 4][nn]);
                mma8(occ[nt], a0, a1, a2, a3, b0, b1);
            }
        }
        __syncwarp();   // done reading P before next jt overwrites
    }

    // ---- normalize + write ctx (tf32-rounded, feeds O-proj) ----
    float inv0 = 1.f / l0, inv1 = 1.f / l1;
    int irow = b * SEQ + i0 + wr + r;
#pragma unroll
    for (int nt = 0; nt < 8; nt++) {
        int col = h * DHEAD + nt * 8 + cq * 2;
        *(float2*)&ctx[(size_t)irow * Hdim + col] =
            make_float2(roundtf(occ[nt][0] * inv0), roundtf(occ[nt][1] * inv0));
        *(float2*)&ctx[(size_t)(irow + 8) * Hdim + col] =
            make_float2(roundtf(occ[nt][2] * inv1), roundtf(occ[nt][3] * inv1));
    }
}

// ---------------- heads: entity logits + pi/pj for relations ------------------
__global__ __launch_bounds__(256) void heads_kernel(
    const float* __restrict__ x, const float* __restrict__ W_ent,
    const float* __restrict__ b_ent, const float* __restrict__ W_rel,
    const float* __restrict__ b_rel, float* __restrict__ ent_out)
{
    int t = blockIdx.x;
    int tid = threadIdx.x;
    __shared__ float xs[Hdim];
    for (int i = tid; i < Hdim; i += 256) xs[i] = x[(size_t)t * Hdim + i];
    __syncthreads();
    int warp = tid >> 5, lane = tid & 31;
    for (int o = warp; o < NEnt + 2 * NRel; o += 8) {
        float s = 0.f;
        if (o < NEnt) {
            for (int k = lane; k < Hdim; k += 32) s += xs[k] * W_ent[(size_t)k * NEnt + o];
        } else if (o < NEnt + NRel) {
            int rr = o - NEnt;
            for (int k = lane; k < Hdim; k += 32) s += xs[k] * W_rel[(size_t)k * NRel + rr];
        } else {
            int rr = o - NEnt - NRel;
            for (int k = lane; k < Hdim; k += 32) s += xs[k] * W_rel[(size_t)(Hdim + k) * NRel + rr];
        }
#pragma unroll
        for (int off = 16; off; off >>= 1) s += __shfl_xor_sync(0xFFFFFFFFu, s, off);
        if (lane == 0) {
            if (o < NEnt)             ent_out[(size_t)t * NEnt + o] = s + b_ent[o];
            else if (o < NEnt + NRel) g_pi[t * NRel + (o - NEnt)] = s;
            else                      g_pj[t * NRel + (o - NEnt - NRel)] = s + b_rel[o - NEnt - NRel];
        }
    }
}

// ---------------- relation broadcast ------------------------------------------
__global__ __launch_bounds__(256) void relation_kernel(float* __restrict__ out)
{
    int bi = blockIdx.x;
    int b = bi >> 9;
    __shared__ float ps[NRel];
    if (threadIdx.x < NRel) ps[threadIdx.x] = g_pi[bi * NRel + threadIdx.x];
    __syncthreads();
    const float* pjb = g_pj + (size_t)(b << 9) * NRel;
    float* o = out + (size_t)bi * SEQ * NRel;
    for (int idx = threadIdx.x; idx < SEQ * NRel; idx += 256) {
        int r = idx % NRel;
        o[idx] = ps[r] + pjb[idx];
    }
}

// ---------------- host orchestration -----------------------------------------
extern "C" void kernel_launch(void* const* d_in, const int* in_sizes, int n_in,
                              void* d_out, int out_size)
{
    const int*   input_ids = (const int*)  d_in[0];
    const int*   attn_mask = (const int*)  d_in[1];
    const float* emb_word  = (const float*)d_in[2];
    const float* emb_pos   = (const float*)d_in[3];
    const float* emb_type  = (const float*)d_in[4];
    const float* emb_ln_g  = (const float*)d_in[5];
    const float* emb_ln_b  = (const float*)d_in[6];
    const float* Wq = (const float*)d_in[7];
    const float* bq = (const float*)d_in[8];
    const float* Wk = (const float*)d_in[9];
    const float* bk = (const float*)d_in[10];
    const float* Wv = (const float*)d_in[11];
    const float* bv = (const float*)d_in[12];
    const float* Wo = (const float*)d_in[13];
    const float* bo = (const float*)d_in[14];
    const float* ln1_g = (const float*)d_in[15];
    const float* ln1_b = (const float*)d_in[16];
    const float* W1 = (const float*)d_in[17];
    const float* b1 = (const float*)d_in[18];
    const float* W2 = (const float*)d_in[19];
    const float* b2 = (const float*)d_in[20];
    const float* ln2_g = (const float*)d_in[21];
    const float* ln2_b = (const float*)d_in[22];
    const float* W_ent = (const float*)d_in[23];
    const float* b_ent = (const float*)d_in[24];
    const float* W_rel = (const float*)d_in[25];
    const float* b_rel = (const float*)d_in[26];

    float *x, *xr, *q, *k, *v, *ctx, *ffn, *part;
    cudaGetSymbolAddress((void**)&x,    g_x);
    cudaGetSymbolAddress((void**)&xr,   g_xr);
    cudaGetSymbolAddress((void**)&q,    g_q);
    cudaGetSymbolAddress((void**)&k,    g_k);
    cudaGetSymbolAddress((void**)&v,    g_v);
    cudaGetSymbolAddress((void**)&ctx,  g_ctx);
    cudaGetSymbolAddress((void**)&ffn,  g_ffn);
    cudaGetSymbolAddress((void**)&part, g_part);

    cudaFuncSetAttribute(attn_flash_kernel,
                         cudaFuncAttributeMaxDynamicSharedMemorySize, ATTN_SMEM);
    cudaFuncSetAttribute(tf32_gemm_kernel,
                         cudaFuncAttributeMaxDynamicSharedMemorySize, GEMM_SMEM);
    cudaFuncSetAttribute(tf32_gemm64_splitk_kernel,
                         cudaFuncAttributeMaxDynamicSharedMemorySize, G64_SMEM);

    embed_ln_kernel<<<MTOK, 256>>>(input_ids, emb_word, emb_pos, emb_type,
                                   emb_ln_g, emb_ln_b);
    abias_kernel<<<(BATCH * SEQ + 255) / 256, 256>>>(attn_mask);

    dim3 gQKV(Hdim / 128, MTOK / 128, 3);
    dim3 gF1(FFdim / 128, MTOK / 128, 1);
    dim3 gSK(Hdim / 128, MTOK / 64, NSPLIT);  // 6 x 32 x 3 = 576 blocks
    dim3 gA(SEQ / 64, BATCH * NHEADS);        // 8 x 48 = 384 blocks

    for (int l = 0; l < NLAY; l++) {
        size_t wHH = (size_t)l * Hdim * Hdim;
        size_t wH  = (size_t)l * Hdim;
        size_t wHF = (size_t)l * Hdim * FFdim;
        tf32_gemm_kernel<<<gQKV, 256, GEMM_SMEM>>>(xr, Wq + wHH, Wk + wHH, Wv + wHH,
                                        bq + wH, bk + wH, bv + wH,
                                        q, k, v, MTOK, Hdim, Hdim, 0, 1);
        attn_flash_kernel<<<gA, 128, ATTN_SMEM>>>(q, k, v, ctx);
        tf32_gemm64_splitk_kernel<<<gSK, 256, G64_SMEM>>>(ctx, Wo + wHH, part,
                                                          MTOK, Hdim, Hdim, Hdim / NSPLIT);
        reduce3_add_ln_kernel<<<MTOK, 256>>>(part, bo + wH, x, ln1_g + wH, ln1_b + wH);
        tf32_gemm_kernel<<<gF1, 256, GEMM_SMEM>>>(xr, W1 + wHF, W1 + wHF, W1 + wHF,
                                       b1 + (size_t)l * FFdim, b1 + (size_t)l * FFdim, b1 + (size_t)l * FFdim,
                                       ffn, ffn, ffn, MTOK, FFdim, Hdim, 1, 1);
        tf32_gemm64_splitk_kernel<<<gSK, 256, G64_SMEM>>>(ffn, W2 + wHF, part,
                                                          MTOK, Hdim, FFdim, FFdim / NSPLIT);
        reduce3_add_ln_kernel<<<MTOK, 256>>>(part, b2 + wH, x, ln2_g + wH, ln2_b + wH);
    }

    float* out = (float*)d_out;
    heads_kernel<<<MTOK, 256>>>(x, W_ent, b_ent, W_rel, b_rel, out);
    relation_kernel<<<MTOK, 256>>>(out + (size_t)MTOK * NEnt);
}